// round 1
// baseline (speedup 1.0000x reference)
#include <cuda_runtime.h>
#include <cstdint>
#include <cstddef>

#define NN 50000
#define NE 800000
#define BASIS 64
#define HID 128
#define NG 512

// Scratch (allocation-free rule: __device__ globals). ~243 MB total.
__device__ __align__(256) float g_dfeat[(size_t)NE * BASIS];
__device__ __align__(256) float g_nf[(size_t)NN * BASIS];
__device__ __align__(256) float g_Ca[(size_t)NN * BASIS];
__device__ __align__(256) float g_Cb[(size_t)NN * BASIS];

__device__ __forceinline__ float fast_tanh(float v) {
    float y;
    asm("tanh.approx.f32 %0, %1;" : "=f"(y) : "f"(v));
    return y;
}

__device__ __forceinline__ void red_add_v4(float* p, float a, float b, float c, float d) {
    asm volatile("red.global.add.v4.f32 [%0], {%1, %2, %3, %4};"
                 :: "l"(p), "f"(a), "f"(b), "f"(c), "f"(d)
                 : "memory");
}

__global__ void __launch_bounds__(256) k_init_C(const int* __restrict__ Z,
                                                const float* __restrict__ embed,
                                                float* __restrict__ C) {
    int idx = blockIdx.x * blockDim.x + threadIdx.x;
    if (idx >= NN * BASIS) return;
    int n = idx >> 6;
    int j = idx & 63;
    C[idx] = embed[Z[n] * BASIS + j];
}

__global__ void __launch_bounds__(256) k_zero(float* __restrict__ p, int n) {
    int i = blockIdx.x * blockDim.x + threadIdx.x;
    if (i < n) p[i] = 0.0f;
}

// out[r,:] = in[r,:] @ W + bias   (W: 64x64 row-major), optional copy of in -> copy_out
__global__ void __launch_bounds__(256) k_matvec(const float* __restrict__ in,
                                                const float* __restrict__ W,
                                                const float* __restrict__ bias,
                                                float* __restrict__ out,
                                                float* __restrict__ copy_out,
                                                int nrows) {
    __shared__ float Ws[BASIS * BASIS];
    __shared__ float bs[BASIS];
    for (int i = threadIdx.x; i < BASIS * BASIS; i += blockDim.x) Ws[i] = W[i];
    if (threadIdx.x < BASIS) bs[threadIdx.x] = bias[threadIdx.x];
    __syncthreads();

    int r = blockIdx.x * blockDim.x + threadIdx.x;
    if (r >= nrows) return;

    float x[BASIS];
    const float4* ip = reinterpret_cast<const float4*>(in + (size_t)r * BASIS);
    float4* cp = copy_out ? reinterpret_cast<float4*>(copy_out + (size_t)r * BASIS) : nullptr;
#pragma unroll
    for (int i = 0; i < BASIS / 4; i++) {
        float4 v = ip[i];
        x[4 * i + 0] = v.x; x[4 * i + 1] = v.y;
        x[4 * i + 2] = v.z; x[4 * i + 3] = v.w;
        if (cp) cp[i] = v;
    }

    float4* op = reinterpret_cast<float4*>(out + (size_t)r * BASIS);
#pragma unroll 1
    for (int j = 0; j < BASIS; j += 4) {
        float a0 = bs[j + 0], a1 = bs[j + 1], a2 = bs[j + 2], a3 = bs[j + 3];
#pragma unroll
        for (int k = 0; k < BASIS; k++) {
            float4 w = *reinterpret_cast<const float4*>(&Ws[k * BASIS + j]);
            a0 += x[k] * w.x; a1 += x[k] * w.y;
            a2 += x[k] * w.z; a3 += x[k] * w.w;
        }
        op[j >> 2] = make_float4(a0, a1, a2, a3);
    }
}

// Per edge: x = nf[src] * dfeat[e]; msg = tanh(x @ fcW); Cout[dst] += msg (atomic v4)
__global__ void __launch_bounds__(256) k_edge(const float* __restrict__ nf,
                                              const float* __restrict__ dfeat,
                                              const int* __restrict__ src,
                                              const int* __restrict__ dst,
                                              const float* __restrict__ fcW,
                                              float* __restrict__ Cout) {
    __shared__ float Ws[BASIS * BASIS];
    for (int i = threadIdx.x; i < BASIS * BASIS; i += blockDim.x) Ws[i] = fcW[i];
    __syncthreads();

    int e = blockIdx.x * blockDim.x + threadIdx.x;
    if (e >= NE) return;

    int s = src[e];
    int d = dst[e];

    float x[BASIS];
    const float4* ap = reinterpret_cast<const float4*>(nf + (size_t)s * BASIS);
    const float4* bp = reinterpret_cast<const float4*>(dfeat + (size_t)e * BASIS);
#pragma unroll
    for (int i = 0; i < BASIS / 4; i++) {
        float4 av = ap[i];
        float4 bv = bp[i];
        x[4 * i + 0] = av.x * bv.x; x[4 * i + 1] = av.y * bv.y;
        x[4 * i + 2] = av.z * bv.z; x[4 * i + 3] = av.w * bv.w;
    }

    float* outp = Cout + (size_t)d * BASIS;
#pragma unroll 1
    for (int j = 0; j < BASIS; j += 4) {
        float a0 = 0.f, a1 = 0.f, a2 = 0.f, a3 = 0.f;
#pragma unroll
        for (int k = 0; k < BASIS; k++) {
            float4 w = *reinterpret_cast<const float4*>(&Ws[k * BASIS + j]);
            a0 += x[k] * w.x; a1 += x[k] * w.y;
            a2 += x[k] * w.z; a3 += x[k] * w.w;
        }
        red_add_v4(outp + j, fast_tanh(a0), fast_tanh(a1), fast_tanh(a2), fast_tanh(a3));
    }
}

// Per node: h = tanh(C @ W1 + b1); o = h @ W2 + b2; out[batch[n]] += o (atomic v4)
__global__ void __launch_bounds__(256) k_readout(const float* __restrict__ C,
                                                 const int* __restrict__ batch,
                                                 const float* __restrict__ W1,
                                                 const float* __restrict__ b1,
                                                 const float* __restrict__ W2,
                                                 const float* __restrict__ b2,
                                                 float* __restrict__ out) {
    __shared__ float W1s[BASIS * HID];   // 32 KB
    __shared__ float W2s[HID * 4];       // 2 KB
    __shared__ float b1s[HID];
    for (int i = threadIdx.x; i < BASIS * HID; i += blockDim.x) W1s[i] = W1[i];
    for (int i = threadIdx.x; i < HID * 4; i += blockDim.x) W2s[i] = W2[i];
    if (threadIdx.x < HID) b1s[threadIdx.x] = b1[threadIdx.x];
    __syncthreads();

    int n = blockIdx.x * blockDim.x + threadIdx.x;
    if (n >= NN) return;

    float x[BASIS];
    const float4* ip = reinterpret_cast<const float4*>(C + (size_t)n * BASIS);
#pragma unroll
    for (int i = 0; i < BASIS / 4; i++) {
        float4 v = ip[i];
        x[4 * i + 0] = v.x; x[4 * i + 1] = v.y;
        x[4 * i + 2] = v.z; x[4 * i + 3] = v.w;
    }

    float o0 = b2[0], o1 = b2[1], o2 = b2[2], o3 = b2[3];
#pragma unroll 1
    for (int j = 0; j < HID; j += 4) {
        float a0 = b1s[j + 0], a1 = b1s[j + 1], a2 = b1s[j + 2], a3 = b1s[j + 3];
#pragma unroll
        for (int k = 0; k < BASIS; k++) {
            float4 w = *reinterpret_cast<const float4*>(&W1s[k * HID + j]);
            a0 += x[k] * w.x; a1 += x[k] * w.y;
            a2 += x[k] * w.z; a3 += x[k] * w.w;
        }
        a0 = fast_tanh(a0); a1 = fast_tanh(a1);
        a2 = fast_tanh(a2); a3 = fast_tanh(a3);
        float4 r0 = *reinterpret_cast<const float4*>(&W2s[(j + 0) * 4]);
        float4 r1 = *reinterpret_cast<const float4*>(&W2s[(j + 1) * 4]);
        float4 r2 = *reinterpret_cast<const float4*>(&W2s[(j + 2) * 4]);
        float4 r3 = *reinterpret_cast<const float4*>(&W2s[(j + 3) * 4]);
        o0 += a0 * r0.x + a1 * r1.x + a2 * r2.x + a3 * r3.x;
        o1 += a0 * r0.y + a1 * r1.y + a2 * r2.y + a3 * r3.y;
        o2 += a0 * r0.z + a1 * r1.z + a2 * r2.z + a3 * r3.z;
        o3 += a0 * r0.w + a1 * r1.w + a2 * r2.w + a3 * r3.w;
    }
    red_add_v4(out + (size_t)batch[n] * 4, o0, o1, o2, o3);
}

extern "C" void kernel_launch(void* const* d_in, const int* in_sizes, int n_in,
                              void* d_out, int out_size) {
    const int*   Z         = (const int*)d_in[0];
    const int*   ei        = (const int*)d_in[1];
    const float* edge_attr = (const float*)d_in[2];
    const int*   batch     = (const int*)d_in[3];
    const float* embed     = (const float*)d_in[4];
    const float* cfW       = (const float*)d_in[5];
    const float* cfb       = (const float*)d_in[6];
    const float* dfW       = (const float*)d_in[7];
    const float* dfb       = (const float*)d_in[8];
    const float* fcW       = (const float*)d_in[9];
    const float* W1        = (const float*)d_in[10];
    const float* b1        = (const float*)d_in[11];
    const float* W2        = (const float*)d_in[12];
    const float* b2        = (const float*)d_in[13];
    const int* src = ei;
    const int* dst = ei + NE;

    float *Ca, *Cb, *nf, *dfeat;
    cudaGetSymbolAddress((void**)&Ca, g_Ca);
    cudaGetSymbolAddress((void**)&Cb, g_Cb);
    cudaGetSymbolAddress((void**)&nf, g_nf);
    cudaGetSymbolAddress((void**)&dfeat, g_dfeat);

    // C0 = embed[Z]
    k_init_C<<<(NN * BASIS + 255) / 256, 256>>>(Z, embed, Ca);
    // d_feat = edge_attr @ dfW + dfb   (loop-invariant, compute once)
    k_matvec<<<(NE + 255) / 256, 256>>>(edge_attr, dfW, dfb, dfeat, nullptr, NE);

    for (int t = 0; t < 3; t++) {
        // nf = Ca @ cfW + cfb  (per-node, 16x cheaper than per-edge); Cb = Ca
        k_matvec<<<(NN + 255) / 256, 256>>>(Ca, cfW, cfb, nf, Cb, NN);
        // Cb[dst] += tanh((nf[src] * dfeat) @ fcW)
        k_edge<<<(NE + 255) / 256, 256>>>(nf, dfeat, src, dst, fcW, Cb);
        float* tmp = Ca; Ca = Cb; Cb = tmp;
    }

    k_zero<<<(NG * 4 + 255) / 256, 256>>>((float*)d_out, NG * 4);
    k_readout<<<(NN + 255) / 256, 256>>>(Ca, batch, W1, b1, W2, b2, (float*)d_out);
}

// round 2
// speedup vs baseline: 1.0885x; 1.0885x over previous
#include <cuda_runtime.h>
#include <cstdint>
#include <cstddef>

#define NN 50000
#define NE 800000
#define BASIS 64
#define HID 128
#define NG 512
#define TILE 256
#define XSTR 257   // padded smem stride (floats)

// Scratch (__device__ globals per allocation rules). ~243 MB.
__device__ __align__(256) float g_dfeat[(size_t)NE * BASIS];
__device__ __align__(256) float g_nf[(size_t)NN * BASIS];
__device__ __align__(256) float g_Ca[(size_t)NN * BASIS];
__device__ __align__(256) float g_Cb[(size_t)NN * BASIS];

__device__ __forceinline__ float fast_tanh(float v) {
    float y;
    asm("tanh.approx.f32 %0, %1;" : "=f"(y) : "f"(v));
    return y;
}

__device__ __forceinline__ void red_add_v4(float* p, float a, float b, float c, float d) {
    asm volatile("red.global.add.v4.f32 [%0], {%1, %2, %3, %4};"
                 :: "l"(p), "f"(a), "f"(b), "f"(c), "f"(d)
                 : "memory");
}

__global__ void __launch_bounds__(256) k_init_C(const int* __restrict__ Z,
                                                const float* __restrict__ embed,
                                                float* __restrict__ C) {
    int idx = blockIdx.x * blockDim.x + threadIdx.x;
    if (idx >= NN * BASIS) return;
    int n = idx >> 6;
    int j = idx & 63;
    C[idx] = embed[Z[n] * BASIS + j];
}

__global__ void __launch_bounds__(256) k_zero(float* __restrict__ p, int n) {
    int i = blockIdx.x * blockDim.x + threadIdx.x;
    if (i < n) p[i] = 0.0f;
}

// ---------------------------------------------------------------------------
// Tiled row-GEMM: out[e,:] = in[e,:] @ W + bias, 256 rows/block.
// Coalesced staging -> smem transposed -> regs -> FFMA -> smem -> coalesced STG.
// Requires nrows % TILE == 0 (NE/TILE = 3125 exactly).
// ---------------------------------------------------------------------------
__global__ void __launch_bounds__(256) k_rowgemm(const float* __restrict__ in,
                                                 const float* __restrict__ W,
                                                 const float* __restrict__ bias,
                                                 float* __restrict__ out) {
    extern __shared__ float sm[];
    float* xs = sm;                       // [64][XSTR]
    float* Ws = sm + BASIS * XSTR;        // [64][64]
    float* bs = Ws + BASIS * BASIS;       // [64]

    int t = threadIdx.x;
    size_t e0 = (size_t)blockIdx.x * TILE;

    for (int i = t; i < BASIS * BASIS; i += 256) Ws[i] = W[i];
    if (t < BASIS) bs[t] = bias[t];

    // Stage input tile: linear coalesced float4 loads -> transposed smem
    const float4* in4 = reinterpret_cast<const float4*>(in + e0 * BASIS);
    for (int i = t; i < TILE * 16; i += 256) {
        float4 v = in4[i];
        int e = i >> 4;
        int k = (i & 15) << 2;
        xs[(k + 0) * XSTR + e] = v.x;
        xs[(k + 1) * XSTR + e] = v.y;
        xs[(k + 2) * XSTR + e] = v.z;
        xs[(k + 3) * XSTR + e] = v.w;
    }
    __syncthreads();

    float x[BASIS];
#pragma unroll
    for (int k = 0; k < BASIS; k++) x[k] = xs[k * XSTR + t];
    __syncthreads();   // xs reused for results below

#pragma unroll 1
    for (int j = 0; j < BASIS; j += 4) {
        float a0 = bs[j + 0], a1 = bs[j + 1], a2 = bs[j + 2], a3 = bs[j + 3];
#pragma unroll
        for (int k = 0; k < BASIS; k++) {
            float4 w = *reinterpret_cast<const float4*>(&Ws[k * BASIS + j]);
            a0 += x[k] * w.x; a1 += x[k] * w.y;
            a2 += x[k] * w.z; a3 += x[k] * w.w;
        }
        xs[(j + 0) * XSTR + t] = a0;
        xs[(j + 1) * XSTR + t] = a1;
        xs[(j + 2) * XSTR + t] = a2;
        xs[(j + 3) * XSTR + t] = a3;
    }
    __syncthreads();

    // Coalesced store
    float4* o4 = reinterpret_cast<float4*>(out + e0 * BASIS);
    for (int i = t; i < TILE * 16; i += 256) {
        int e = i >> 4;
        int k = (i & 15) << 2;
        o4[i] = make_float4(xs[(k + 0) * XSTR + e], xs[(k + 1) * XSTR + e],
                            xs[(k + 2) * XSTR + e], xs[(k + 3) * XSTR + e]);
    }
}

// ---------------------------------------------------------------------------
// Edge kernel: x = nf[src]*dfeat[e]; msg = tanh(x @ fcW); Cout[dst] += msg.
// Staged like k_rowgemm; gather becomes 2-rows-per-warp coalesced.
// ---------------------------------------------------------------------------
__global__ void __launch_bounds__(256) k_edge(const float* __restrict__ nf,
                                              const float* __restrict__ dfeat,
                                              const int* __restrict__ src,
                                              const int* __restrict__ dst,
                                              const float* __restrict__ fcW,
                                              float* __restrict__ Cout) {
    extern __shared__ float sm[];
    float* xs = sm;                        // [64][XSTR]
    float* Ws = sm + BASIS * XSTR;         // [64][64]
    int* sIdx = reinterpret_cast<int*>(Ws + BASIS * BASIS);   // [256]
    int* dIdx = sIdx + TILE;                                   // [256]

    int t = threadIdx.x;
    size_t e0 = (size_t)blockIdx.x * TILE;

    for (int i = t; i < BASIS * BASIS; i += 256) Ws[i] = fcW[i];
    sIdx[t] = src[e0 + t];
    dIdx[t] = dst[e0 + t];
    __syncthreads();

    const float4* nf4 = reinterpret_cast<const float4*>(nf);
    const float4* df4 = reinterpret_cast<const float4*>(dfeat + e0 * BASIS);
    for (int i = t; i < TILE * 16; i += 256) {
        int e = i >> 4;
        int k4 = i & 15;
        float4 a = nf4[(size_t)sIdx[e] * 16 + k4];
        float4 b = df4[i];
        int k = k4 << 2;
        xs[(k + 0) * XSTR + e] = a.x * b.x;
        xs[(k + 1) * XSTR + e] = a.y * b.y;
        xs[(k + 2) * XSTR + e] = a.z * b.z;
        xs[(k + 3) * XSTR + e] = a.w * b.w;
    }
    __syncthreads();

    float x[BASIS];
#pragma unroll
    for (int k = 0; k < BASIS; k++) x[k] = xs[k * XSTR + t];

    float* outp = Cout + (size_t)dIdx[t] * BASIS;
#pragma unroll 1
    for (int j = 0; j < BASIS; j += 4) {
        float a0 = 0.f, a1 = 0.f, a2 = 0.f, a3 = 0.f;
#pragma unroll
        for (int k = 0; k < BASIS; k++) {
            float4 w = *reinterpret_cast<const float4*>(&Ws[k * BASIS + j]);
            a0 += x[k] * w.x; a1 += x[k] * w.y;
            a2 += x[k] * w.z; a3 += x[k] * w.w;
        }
        red_add_v4(outp + j, fast_tanh(a0), fast_tanh(a1), fast_tanh(a2), fast_tanh(a3));
    }
}

// nf = C @ cfW + cfb (per-node), plus copy C -> Cb. Small (NN rows).
__global__ void __launch_bounds__(256) k_nodemv(const float* __restrict__ in,
                                                const float* __restrict__ W,
                                                const float* __restrict__ bias,
                                                float* __restrict__ out,
                                                float* __restrict__ copy_out,
                                                int nrows) {
    __shared__ float Ws[BASIS * BASIS];
    __shared__ float bs[BASIS];
    for (int i = threadIdx.x; i < BASIS * BASIS; i += blockDim.x) Ws[i] = W[i];
    if (threadIdx.x < BASIS) bs[threadIdx.x] = bias[threadIdx.x];
    __syncthreads();

    int r = blockIdx.x * blockDim.x + threadIdx.x;
    if (r >= nrows) return;

    float x[BASIS];
    const float4* ip = reinterpret_cast<const float4*>(in + (size_t)r * BASIS);
    float4* cp = reinterpret_cast<float4*>(copy_out + (size_t)r * BASIS);
#pragma unroll
    for (int i = 0; i < BASIS / 4; i++) {
        float4 v = ip[i];
        x[4 * i + 0] = v.x; x[4 * i + 1] = v.y;
        x[4 * i + 2] = v.z; x[4 * i + 3] = v.w;
        cp[i] = v;
    }

    float4* op = reinterpret_cast<float4*>(out + (size_t)r * BASIS);
#pragma unroll 1
    for (int j = 0; j < BASIS; j += 4) {
        float a0 = bs[j + 0], a1 = bs[j + 1], a2 = bs[j + 2], a3 = bs[j + 3];
#pragma unroll
        for (int k = 0; k < BASIS; k++) {
            float4 w = *reinterpret_cast<const float4*>(&Ws[k * BASIS + j]);
            a0 += x[k] * w.x; a1 += x[k] * w.y;
            a2 += x[k] * w.z; a3 += x[k] * w.w;
        }
        op[j >> 2] = make_float4(a0, a1, a2, a3);
    }
}

// Readout: h = tanh(C @ W1 + b1); o = h @ W2 + b2; out[batch[n]] += o
__global__ void __launch_bounds__(256) k_readout(const float* __restrict__ C,
                                                 const int* __restrict__ batch,
                                                 const float* __restrict__ W1,
                                                 const float* __restrict__ b1,
                                                 const float* __restrict__ W2,
                                                 const float* __restrict__ b2,
                                                 float* __restrict__ out) {
    __shared__ float W1s[BASIS * HID];
    __shared__ float W2s[HID * 4];
    __shared__ float b1s[HID];
    for (int i = threadIdx.x; i < BASIS * HID; i += blockDim.x) W1s[i] = W1[i];
    for (int i = threadIdx.x; i < HID * 4; i += blockDim.x) W2s[i] = W2[i];
    if (threadIdx.x < HID) b1s[threadIdx.x] = b1[threadIdx.x];
    __syncthreads();

    int n = blockIdx.x * blockDim.x + threadIdx.x;
    if (n >= NN) return;

    float x[BASIS];
    const float4* ip = reinterpret_cast<const float4*>(C + (size_t)n * BASIS);
#pragma unroll
    for (int i = 0; i < BASIS / 4; i++) {
        float4 v = ip[i];
        x[4 * i + 0] = v.x; x[4 * i + 1] = v.y;
        x[4 * i + 2] = v.z; x[4 * i + 3] = v.w;
    }

    float o0 = b2[0], o1 = b2[1], o2 = b2[2], o3 = b2[3];
#pragma unroll 1
    for (int j = 0; j < HID; j += 4) {
        float a0 = b1s[j + 0], a1 = b1s[j + 1], a2 = b1s[j + 2], a3 = b1s[j + 3];
#pragma unroll
        for (int k = 0; k < BASIS; k++) {
            float4 w = *reinterpret_cast<const float4*>(&W1s[k * HID + j]);
            a0 += x[k] * w.x; a1 += x[k] * w.y;
            a2 += x[k] * w.z; a3 += x[k] * w.w;
        }
        a0 = fast_tanh(a0); a1 = fast_tanh(a1);
        a2 = fast_tanh(a2); a3 = fast_tanh(a3);
        float4 r0 = *reinterpret_cast<const float4*>(&W2s[(j + 0) * 4]);
        float4 r1 = *reinterpret_cast<const float4*>(&W2s[(j + 1) * 4]);
        float4 r2 = *reinterpret_cast<const float4*>(&W2s[(j + 2) * 4]);
        float4 r3 = *reinterpret_cast<const float4*>(&W2s[(j + 3) * 4]);
        o0 += a0 * r0.x + a1 * r1.x + a2 * r2.x + a3 * r3.x;
        o1 += a0 * r0.y + a1 * r1.y + a2 * r2.y + a3 * r3.y;
        o2 += a0 * r0.z + a1 * r1.z + a2 * r2.z + a3 * r3.z;
        o3 += a0 * r0.w + a1 * r1.w + a2 * r2.w + a3 * r3.w;
    }
    red_add_v4(out + (size_t)batch[n] * 4, o0, o1, o2, o3);
}

extern "C" void kernel_launch(void* const* d_in, const int* in_sizes, int n_in,
                              void* d_out, int out_size) {
    const int*   Z         = (const int*)d_in[0];
    const int*   ei        = (const int*)d_in[1];
    const float* edge_attr = (const float*)d_in[2];
    const int*   batch     = (const int*)d_in[3];
    const float* embed     = (const float*)d_in[4];
    const float* cfW       = (const float*)d_in[5];
    const float* cfb       = (const float*)d_in[6];
    const float* dfW       = (const float*)d_in[7];
    const float* dfb       = (const float*)d_in[8];
    const float* fcW       = (const float*)d_in[9];
    const float* W1        = (const float*)d_in[10];
    const float* b1        = (const float*)d_in[11];
    const float* W2        = (const float*)d_in[12];
    const float* b2        = (const float*)d_in[13];
    const int* src = ei;
    const int* dst = ei + NE;

    float *Ca, *Cb, *nf, *dfeat;
    cudaGetSymbolAddress((void**)&Ca, g_Ca);
    cudaGetSymbolAddress((void**)&Cb, g_Cb);
    cudaGetSymbolAddress((void**)&nf, g_nf);
    cudaGetSymbolAddress((void**)&dfeat, g_dfeat);

    const int SM_GEMM = (BASIS * XSTR + BASIS * BASIS + BASIS) * 4;          // 82432 B
    const int SM_EDGE = (BASIS * XSTR + BASIS * BASIS) * 4 + 2 * TILE * 4;   // 84224 B
    cudaFuncSetAttribute(k_rowgemm, cudaFuncAttributeMaxDynamicSharedMemorySize, SM_GEMM);
    cudaFuncSetAttribute(k_edge, cudaFuncAttributeMaxDynamicSharedMemorySize, SM_EDGE);

    // C0 = embed[Z]
    k_init_C<<<(NN * BASIS + 255) / 256, 256>>>(Z, embed, Ca);
    // d_feat = edge_attr @ dfW + dfb (loop-invariant)
    k_rowgemm<<<NE / TILE, 256, SM_GEMM>>>(edge_attr, dfW, dfb, dfeat);

    for (int t = 0; t < 3; t++) {
        k_nodemv<<<(NN + 255) / 256, 256>>>(Ca, cfW, cfb, nf, Cb, NN);
        k_edge<<<NE / TILE, 256, SM_EDGE>>>(nf, dfeat, src, dst, fcW, Cb);
        float* tmp = Ca; Ca = Cb; Cb = tmp;
    }

    k_zero<<<(NG * 4 + 255) / 256, 256>>>((float*)d_out, NG * 4);
    k_readout<<<(NN + 255) / 256, 256>>>(Ca, batch, W1, b1, W2, b2, (float*)d_out);
}

// round 3
// speedup vs baseline: 1.4490x; 1.3312x over previous
#include <cuda_runtime.h>
#include <cstdint>
#include <cstddef>

#define NN 50000
#define NE 800000
#define BASIS 64
#define HID 128
#define NG 512
#define TILE 256
#define XST 68          // smem stride (floats) for edge-tile

// Scratch (__device__ globals per allocation rules).
__device__ __align__(256) float g_dfeat[(size_t)NE * BASIS];
__device__ __align__(256) float g_nf[(size_t)NN * BASIS];
__device__ __align__(256) float g_Ca[(size_t)NN * BASIS];
__device__ __align__(256) float g_Cb[(size_t)NN * BASIS];
// Pre-permuted tf32 hi/lo B-fragment tables: [kt 8][nt 8][lane 32][2]
__device__ __align__(256) float g_fcWhi[4096];
__device__ __align__(256) float g_fcWlo[4096];
__device__ __align__(256) float g_dfWhi[4096];
__device__ __align__(256) float g_dfWlo[4096];

__device__ __forceinline__ float fast_tanh(float v) {
    float y;
    asm("tanh.approx.f32 %0, %1;" : "=f"(y) : "f"(v));
    return y;
}
__device__ __forceinline__ float to_tf32(float x) {
    float y;
    asm("cvt.rna.tf32.f32 %0, %1;" : "=f"(y) : "f"(x));
    return y;
}
__device__ __forceinline__ void red_add_v4(float* p, float a, float b, float c, float d) {
    asm volatile("red.global.add.v4.f32 [%0], {%1, %2, %3, %4};"
                 :: "l"(p), "f"(a), "f"(b), "f"(c), "f"(d) : "memory");
}
__device__ __forceinline__ void mma_tf32(float* d, const float* a, const float2 b) {
    asm volatile(
        "mma.sync.aligned.m16n8k8.row.col.f32.tf32.tf32.f32 "
        "{%0,%1,%2,%3}, {%4,%5,%6,%7}, {%8,%9}, {%0,%1,%2,%3};"
        : "+f"(d[0]), "+f"(d[1]), "+f"(d[2]), "+f"(d[3])
        : "r"(__float_as_uint(a[0])), "r"(__float_as_uint(a[1])),
          "r"(__float_as_uint(a[2])), "r"(__float_as_uint(a[3])),
          "r"(__float_as_uint(b.x)), "r"(__float_as_uint(b.y)));
}

// Build permuted tf32 hi/lo fragment tables for a 64x64 W (out = x @ W).
__global__ void __launch_bounds__(256) k_prep(const float* __restrict__ fcW,
                                              const float* __restrict__ dfW) {
    for (int idx = threadIdx.x; idx < 4096; idx += 256) {
        int kt = idx >> 9;
        int nt = (idx >> 6) & 7;
        int lane = (idx >> 1) & 31;
        int hv = idx & 1;                       // b0 / b1
        int row = kt * 8 + (lane & 3) + (hv ? 4 : 0);   // k index
        int col = nt * 8 + (lane >> 2);                 // n index
        float w = fcW[row * BASIS + col];
        float wh = to_tf32(w);
        g_fcWhi[idx] = wh;
        g_fcWlo[idx] = to_tf32(w - wh);
        w = dfW[row * BASIS + col];
        wh = to_tf32(w);
        g_dfWhi[idx] = wh;
        g_dfWlo[idx] = to_tf32(w - wh);
    }
}

__global__ void __launch_bounds__(256) k_init_C(const int* __restrict__ Z,
                                                const float* __restrict__ embed,
                                                float* __restrict__ C) {
    int idx = blockIdx.x * blockDim.x + threadIdx.x;
    if (idx >= NN * BASIS) return;
    C[idx] = embed[Z[idx >> 6] * BASIS + (idx & 63)];
}

__global__ void __launch_bounds__(256) k_zero(float* __restrict__ p, int n) {
    int i = blockIdx.x * blockDim.x + threadIdx.x;
    if (i < n) p[i] = 0.0f;
}

// ---------------------------------------------------------------------------
// Shared mainloop: acc[mt][nt][4] += 3xTF32( xs-tile , Wperm ). 8 warps, 32
// edges/warp (2 m-tiles of 16), 64x64 W. A-frags from xs (stride XST),
// B-frags from permuted smem tables (conflict-free LDS.64).
// ---------------------------------------------------------------------------
__device__ __forceinline__ void mma_mainloop(const float* __restrict__ xs,
                                             const float* __restrict__ whi,
                                             const float* __restrict__ wlo,
                                             int wb, int r, int c,
                                             float acc[2][8][4]) {
#pragma unroll
    for (int kt = 0; kt < 8; kt++) {
        float ah[2][4], al[2][4];
#pragma unroll
        for (int mt = 0; mt < 2; mt++) {
            int e = wb + mt * 16 + r;
            int kc = kt * 8 + c;
            float v0 = xs[(e + 0) * XST + kc + 0];
            float v1 = xs[(e + 8) * XST + kc + 0];
            float v2 = xs[(e + 0) * XST + kc + 4];
            float v3 = xs[(e + 8) * XST + kc + 4];
            ah[mt][0] = to_tf32(v0); al[mt][0] = to_tf32(v0 - ah[mt][0]);
            ah[mt][1] = to_tf32(v1); al[mt][1] = to_tf32(v1 - ah[mt][1]);
            ah[mt][2] = to_tf32(v2); al[mt][2] = to_tf32(v2 - ah[mt][2]);
            ah[mt][3] = to_tf32(v3); al[mt][3] = to_tf32(v3 - ah[mt][3]);
        }
#pragma unroll
        for (int nt = 0; nt < 8; nt++) {
            int bi = ((kt * 8 + nt) * 32 + (r * 4 + c)) * 2;
            float2 bh = *reinterpret_cast<const float2*>(&whi[bi]);
            float2 bl = *reinterpret_cast<const float2*>(&wlo[bi]);
#pragma unroll
            for (int mt = 0; mt < 2; mt++) {
                mma_tf32(acc[mt][nt], ah[mt], bh);
                mma_tf32(acc[mt][nt], al[mt], bh);
                mma_tf32(acc[mt][nt], ah[mt], bl);
            }
        }
    }
}

// dfeat = edge_attr @ dfW + dfb  (tensor-core tiled GEMM, coalesced I/O)
__global__ void __launch_bounds__(256, 2) k_dfeat(const float* __restrict__ in,
                                                  const float* __restrict__ bias,
                                                  float* __restrict__ out) {
    extern __shared__ float sm[];
    float* xs  = sm;                    // [256][68]
    float* whi = sm + TILE * XST;       // [4096]
    float* wlo = whi + 4096;            // [4096]
    float* bs  = wlo + 4096;            // [64]

    int t = threadIdx.x;
    int lane = t & 31;
    int wb = (t >> 5) * 32;
    int r = lane >> 2, c = lane & 3;
    size_t e0 = (size_t)blockIdx.x * TILE;

    for (int i = t; i < 4096; i += 256) { whi[i] = g_dfWhi[i]; wlo[i] = g_dfWlo[i]; }
    if (t < BASIS) bs[t] = bias[t];

    const float4* in4 = reinterpret_cast<const float4*>(in + e0 * BASIS);
    for (int i = t; i < TILE * 16; i += 256) {
        *reinterpret_cast<float4*>(&xs[(i >> 4) * XST + ((i & 15) << 2)]) = in4[i];
    }
    __syncthreads();

    float acc[2][8][4];
#pragma unroll
    for (int mt = 0; mt < 2; mt++)
#pragma unroll
        for (int nt = 0; nt < 8; nt++)
#pragma unroll
            for (int q = 0; q < 4; q++) acc[mt][nt][q] = 0.0f;

    mma_mainloop(xs, whi, wlo, wb, r, c, acc);
    __syncthreads();   // reuse xs for output

#pragma unroll
    for (int mt = 0; mt < 2; mt++)
#pragma unroll
        for (int nt = 0; nt < 8; nt++) {
            int col = nt * 8 + 2 * c;
            int e = wb + mt * 16 + r;
            float b0 = bs[col], b1 = bs[col + 1];
            *reinterpret_cast<float2*>(&xs[e * XST + col]) =
                make_float2(acc[mt][nt][0] + b0, acc[mt][nt][1] + b1);
            *reinterpret_cast<float2*>(&xs[(e + 8) * XST + col]) =
                make_float2(acc[mt][nt][2] + b0, acc[mt][nt][3] + b1);
        }
    __syncthreads();

    float4* o4 = reinterpret_cast<float4*>(out + e0 * BASIS);
    for (int i = t; i < TILE * 16; i += 256) {
        o4[i] = *reinterpret_cast<const float4*>(&xs[(i >> 4) * XST + ((i & 15) << 2)]);
    }
}

// Edge kernel: Cout[dst] += tanh( (nf[src] * dfeat) @ fcW )  (tensor cores)
__global__ void __launch_bounds__(256, 2) k_edge(const float* __restrict__ nf,
                                                 const float* __restrict__ dfeat,
                                                 const int* __restrict__ src,
                                                 const int* __restrict__ dst,
                                                 float* __restrict__ Cout) {
    extern __shared__ float sm[];
    float* xs  = sm;                    // [256][68]
    float* whi = sm + TILE * XST;       // [4096]
    float* wlo = whi + 4096;            // [4096]
    int* sIdx  = reinterpret_cast<int*>(wlo + 4096);  // [256]
    int* dIdx  = sIdx + TILE;                          // [256]

    int t = threadIdx.x;
    int lane = t & 31;
    int wb = (t >> 5) * 32;
    int r = lane >> 2, c = lane & 3;
    size_t e0 = (size_t)blockIdx.x * TILE;

    for (int i = t; i < 4096; i += 256) { whi[i] = g_fcWhi[i]; wlo[i] = g_fcWlo[i]; }
    sIdx[t] = src[e0 + t];
    dIdx[t] = dst[e0 + t];
    __syncthreads();

    const float4* nf4 = reinterpret_cast<const float4*>(nf);
    const float4* df4 = reinterpret_cast<const float4*>(dfeat + e0 * BASIS);
    for (int i = t; i < TILE * 16; i += 256) {
        int e = i >> 4, k4 = i & 15;
        float4 a = nf4[(size_t)sIdx[e] * 16 + k4];
        float4 b = df4[i];
        *reinterpret_cast<float4*>(&xs[e * XST + (k4 << 2)]) =
            make_float4(a.x * b.x, a.y * b.y, a.z * b.z, a.w * b.w);
    }
    __syncthreads();

    float acc[2][8][4];
#pragma unroll
    for (int mt = 0; mt < 2; mt++)
#pragma unroll
        for (int nt = 0; nt < 8; nt++)
#pragma unroll
            for (int q = 0; q < 4; q++) acc[mt][nt][q] = 0.0f;

    mma_mainloop(xs, whi, wlo, wb, r, c, acc);

    // Epilogue: tanh -> pair up lanes (lane, lane^1) -> red.v4 scatter
#pragma unroll
    for (int mt = 0; mt < 2; mt++) {
        int eA = wb + mt * 16 + r;
        float* pA = Cout + (size_t)dIdx[eA] * BASIS;
        float* pB = Cout + (size_t)dIdx[eA + 8] * BASIS;
#pragma unroll
        for (int nt = 0; nt < 8; nt++) {
            float t0 = fast_tanh(acc[mt][nt][0]);
            float t1 = fast_tanh(acc[mt][nt][1]);
            float t2 = fast_tanh(acc[mt][nt][2]);
            float t3 = fast_tanh(acc[mt][nt][3]);
            float p0 = __shfl_xor_sync(0xffffffffu, t0, 1);
            float p1 = __shfl_xor_sync(0xffffffffu, t1, 1);
            float p2 = __shfl_xor_sync(0xffffffffu, t2, 1);
            float p3 = __shfl_xor_sync(0xffffffffu, t3, 1);
            if ((lane & 1) == 0) {
                int col = nt * 8 + 2 * c;   // c even here
                red_add_v4(pA + col, t0, t1, p0, p1);
                red_add_v4(pB + col, t2, t3, p2, p3);
            }
        }
    }
}

// nf = C @ cfW + cfb (per-node), plus copy C -> Cb.
__global__ void __launch_bounds__(256) k_nodemv(const float* __restrict__ in,
                                                const float* __restrict__ W,
                                                const float* __restrict__ bias,
                                                float* __restrict__ out,
                                                float* __restrict__ copy_out,
                                                int nrows) {
    __shared__ float Ws[BASIS * BASIS];
    __shared__ float bs[BASIS];
    for (int i = threadIdx.x; i < BASIS * BASIS; i += blockDim.x) Ws[i] = W[i];
    if (threadIdx.x < BASIS) bs[threadIdx.x] = bias[threadIdx.x];
    __syncthreads();

    int rI = blockIdx.x * blockDim.x + threadIdx.x;
    if (rI >= nrows) return;

    float x[BASIS];
    const float4* ip = reinterpret_cast<const float4*>(in + (size_t)rI * BASIS);
    float4* cp = reinterpret_cast<float4*>(copy_out + (size_t)rI * BASIS);
#pragma unroll
    for (int i = 0; i < BASIS / 4; i++) {
        float4 v = ip[i];
        x[4 * i + 0] = v.x; x[4 * i + 1] = v.y;
        x[4 * i + 2] = v.z; x[4 * i + 3] = v.w;
        cp[i] = v;
    }

    float4* op = reinterpret_cast<float4*>(out + (size_t)rI * BASIS);
#pragma unroll 1
    for (int j = 0; j < BASIS; j += 4) {
        float a0 = bs[j + 0], a1 = bs[j + 1], a2 = bs[j + 2], a3 = bs[j + 3];
#pragma unroll
        for (int k = 0; k < BASIS; k++) {
            float4 w = *reinterpret_cast<const float4*>(&Ws[k * BASIS + j]);
            a0 += x[k] * w.x; a1 += x[k] * w.y;
            a2 += x[k] * w.z; a3 += x[k] * w.w;
        }
        op[j >> 2] = make_float4(a0, a1, a2, a3);
    }
}

// Readout: h = tanh(C @ W1 + b1); o = h @ W2 + b2; out[batch[n]] += o
__global__ void __launch_bounds__(256) k_readout(const float* __restrict__ C,
                                                 const int* __restrict__ batch,
                                                 const float* __restrict__ W1,
                                                 const float* __restrict__ b1,
                                                 const float* __restrict__ W2,
                                                 const float* __restrict__ b2,
                                                 float* __restrict__ out) {
    __shared__ float W1s[BASIS * HID];
    __shared__ float W2s[HID * 4];
    __shared__ float b1s[HID];
    for (int i = threadIdx.x; i < BASIS * HID; i += blockDim.x) W1s[i] = W1[i];
    for (int i = threadIdx.x; i < HID * 4; i += blockDim.x) W2s[i] = W2[i];
    if (threadIdx.x < HID) b1s[threadIdx.x] = b1[threadIdx.x];
    __syncthreads();

    int n = blockIdx.x * blockDim.x + threadIdx.x;
    if (n >= NN) return;

    float x[BASIS];
    const float4* ip = reinterpret_cast<const float4*>(C + (size_t)n * BASIS);
#pragma unroll
    for (int i = 0; i < BASIS / 4; i++) {
        float4 v = ip[i];
        x[4 * i + 0] = v.x; x[4 * i + 1] = v.y;
        x[4 * i + 2] = v.z; x[4 * i + 3] = v.w;
    }

    float o0 = b2[0], o1 = b2[1], o2 = b2[2], o3 = b2[3];
#pragma unroll 1
    for (int j = 0; j < HID; j += 4) {
        float a0 = b1s[j + 0], a1 = b1s[j + 1], a2 = b1s[j + 2], a3 = b1s[j + 3];
#pragma unroll
        for (int k = 0; k < BASIS; k++) {
            float4 w = *reinterpret_cast<const float4*>(&W1s[k * HID + j]);
            a0 += x[k] * w.x; a1 += x[k] * w.y;
            a2 += x[k] * w.z; a3 += x[k] * w.w;
        }
        a0 = fast_tanh(a0); a1 = fast_tanh(a1);
        a2 = fast_tanh(a2); a3 = fast_tanh(a3);
        float4 r0 = *reinterpret_cast<const float4*>(&W2s[(j + 0) * 4]);
        float4 r1 = *reinterpret_cast<const float4*>(&W2s[(j + 1) * 4]);
        float4 r2 = *reinterpret_cast<const float4*>(&W2s[(j + 2) * 4]);
        float4 r3 = *reinterpret_cast<const float4*>(&W2s[(j + 3) * 4]);
        o0 += a0 * r0.x + a1 * r1.x + a2 * r2.x + a3 * r3.x;
        o1 += a0 * r0.y + a1 * r1.y + a2 * r2.y + a3 * r3.y;
        o2 += a0 * r0.z + a1 * r1.z + a2 * r2.z + a3 * r3.z;
        o3 += a0 * r0.w + a1 * r1.w + a2 * r2.w + a3 * r3.w;
    }
    red_add_v4(out + (size_t)batch[n] * 4, o0, o1, o2, o3);
}

extern "C" void kernel_launch(void* const* d_in, const int* in_sizes, int n_in,
                              void* d_out, int out_size) {
    const int*   Z         = (const int*)d_in[0];
    const int*   ei        = (const int*)d_in[1];
    const float* edge_attr = (const float*)d_in[2];
    const int*   batch     = (const int*)d_in[3];
    const float* embed     = (const float*)d_in[4];
    const float* cfW       = (const float*)d_in[5];
    const float* cfb       = (const float*)d_in[6];
    const float* dfW       = (const float*)d_in[7];
    const float* dfb       = (const float*)d_in[8];
    const float* fcW       = (const float*)d_in[9];
    const float* W1        = (const float*)d_in[10];
    const float* b1        = (const float*)d_in[11];
    const float* W2        = (const float*)d_in[12];
    const float* b2        = (const float*)d_in[13];
    const int* src = ei;
    const int* dst = ei + NE;

    float *Ca, *Cb, *nf, *dfeat;
    cudaGetSymbolAddress((void**)&Ca, g_Ca);
    cudaGetSymbolAddress((void**)&Cb, g_Cb);
    cudaGetSymbolAddress((void**)&nf, g_nf);
    cudaGetSymbolAddress((void**)&dfeat, g_dfeat);

    const int SM_DF = (TILE * XST + 2 * 4096 + 64) * 4;                // 102656
    const int SM_ED = (TILE * XST + 2 * 4096) * 4 + 2 * TILE * 4;      // 104448
    cudaFuncSetAttribute(k_dfeat, cudaFuncAttributeMaxDynamicSharedMemorySize, SM_DF);
    cudaFuncSetAttribute(k_edge, cudaFuncAttributeMaxDynamicSharedMemorySize, SM_ED);

    k_prep<<<1, 256>>>(fcW, dfW);
    k_init_C<<<(NN * BASIS + 255) / 256, 256>>>(Z, embed, Ca);
    k_dfeat<<<NE / TILE, 256, SM_DF>>>(edge_attr, dfb, dfeat);

    for (int t = 0; t < 3; t++) {
        k_nodemv<<<(NN + 255) / 256, 256>>>(Ca, cfW, cfb, nf, Cb, NN);
        k_edge<<<NE / TILE, 256, SM_ED>>>(nf, dfeat, src, dst, Cb);
        float* tmp = Ca; Ca = Cb; Cb = tmp;
    }

    k_zero<<<(NG * 4 + 255) / 256, 256>>>((float*)d_out, NG * 4);
    k_readout<<<(NN + 255) / 256, 256>>>(Ca, batch, W1, b1, W2, b2, (float*)d_out);
}

// round 4
// speedup vs baseline: 1.8431x; 1.2720x over previous
#include <cuda_runtime.h>
#include <cuda_fp16.h>
#include <cstdint>
#include <cstddef>

#define NN 50000
#define NE 800000
#define BASIS 64
#define HID 128
#define NG 512
#define TILE 256
#define XST 68          // smem stride (floats) for staged tiles

// Scratch (__device__ globals per allocation rules).
__device__ __align__(256) float g_dfeat[(size_t)NE * BASIS];
__device__ __align__(256) float g_nf[(size_t)NN * BASIS];
__device__ __align__(256) float g_Ca[(size_t)NN * BASIS];
// fp16 hi/lo B-fragment tables: [kc 4][nt 8][lane 32] -> uint2 (4 half each)
__device__ __align__(256) uint2 g_fcWhi[1024];
__device__ __align__(256) uint2 g_fcWlo[1024];
__device__ __align__(256) uint2 g_dfWhi[1024];
__device__ __align__(256) uint2 g_dfWlo[1024];
__device__ __align__(256) uint2 g_cfWhi[1024];
__device__ __align__(256) uint2 g_cfWlo[1024];

__device__ __forceinline__ float fast_tanh(float v) {
    float y;
    asm("tanh.approx.f32 %0, %1;" : "=f"(y) : "f"(v));
    return y;
}
__device__ __forceinline__ void red_add_v4(float* p, float a, float b, float c, float d) {
    asm volatile("red.global.add.v4.f32 [%0], {%1, %2, %3, %4};"
                 :: "l"(p), "f"(a), "f"(b), "f"(c), "f"(d) : "memory");
}
__device__ __forceinline__ unsigned pack_h2(float x, float y) {
    __half2 h = __floats2half2_rn(x, y);
    return *reinterpret_cast<unsigned*>(&h);
}
__device__ __forceinline__ unsigned split_hi(float2 v, float2& rest) {
    __half2 h = __floats2half2_rn(v.x, v.y);
    rest.x = v.x - __low2float(h);
    rest.y = v.y - __high2float(h);
    return *reinterpret_cast<unsigned*>(&h);
}
__device__ __forceinline__ void mma_fp16(float* d, const unsigned* a, const uint2 b) {
    asm volatile(
        "mma.sync.aligned.m16n8k16.row.col.f32.f16.f16.f32 "
        "{%0,%1,%2,%3}, {%4,%5,%6,%7}, {%8,%9}, {%0,%1,%2,%3};"
        : "+f"(d[0]), "+f"(d[1]), "+f"(d[2]), "+f"(d[3])
        : "r"(a[0]), "r"(a[1]), "r"(a[2]), "r"(a[3]),
          "r"(b.x), "r"(b.y));
}

// Build permuted fp16 hi/lo B-fragment tables for 64x64 weights (out = x @ W).
// Entry (kc, nt, lane): n = nt*8 + lane/4; k0 = kc*16 + (lane%4)*2;
// reg.x = {W[k0][n], W[k0+1][n]}, reg.y = {W[k0+8][n], W[k0+9][n]}.
__global__ void __launch_bounds__(256) k_prep(const float* __restrict__ fcW,
                                              const float* __restrict__ dfW,
                                              const float* __restrict__ cfW) {
    for (int idx = threadIdx.x; idx < 1024; idx += 256) {
        int kc = idx >> 8;
        int nt = (idx >> 5) & 7;
        int lane = idx & 31;
        int n = nt * 8 + (lane >> 2);
        int k0 = kc * 16 + (lane & 3) * 2;
        const float* Ws[3] = {fcW, dfW, cfW};
        uint2* hiT[3] = {g_fcWhi, g_dfWhi, g_cfWhi};
        uint2* loT[3] = {g_fcWlo, g_dfWlo, g_cfWlo};
#pragma unroll
        for (int w = 0; w < 3; w++) {
            float w00 = Ws[w][(k0 + 0) * BASIS + n];
            float w01 = Ws[w][(k0 + 1) * BASIS + n];
            float w10 = Ws[w][(k0 + 8) * BASIS + n];
            float w11 = Ws[w][(k0 + 9) * BASIS + n];
            float2 r0, r1;
            uint2 hi, lo;
            hi.x = split_hi(make_float2(w00, w01), r0);
            hi.y = split_hi(make_float2(w10, w11), r1);
            lo.x = pack_h2(r0.x, r0.y);
            lo.y = pack_h2(r1.x, r1.y);
            hiT[w][idx] = hi;
            loT[w][idx] = lo;
        }
    }
}

__global__ void __launch_bounds__(256) k_init_C(const int* __restrict__ Z,
                                                const float* __restrict__ embed,
                                                float* __restrict__ C) {
    int idx = blockIdx.x * blockDim.x + threadIdx.x;
    if (idx >= NN * BASIS) return;
    C[idx] = embed[Z[idx >> 6] * BASIS + (idx & 63)];
}

__global__ void __launch_bounds__(256) k_zero(float* __restrict__ p, int n) {
    int i = blockIdx.x * blockDim.x + threadIdx.x;
    if (i < n) p[i] = 0.0f;
}

// ---------------------------------------------------------------------------
// fp16-split mainloop: acc[mt][nt][4] += xs-tile @ W (3-product Markidis).
// 8 warps, 32 rows/warp (2 m-tiles of 16). A from xs (fp32, stride XST),
// B from permuted uint2 tables in smem.
// ---------------------------------------------------------------------------
__device__ __forceinline__ void mma_mainloop(const float* __restrict__ xs,
                                             const uint2* __restrict__ whi,
                                             const uint2* __restrict__ wlo,
                                             int wb, int lane,
                                             float acc[2][8][4]) {
    int r = lane >> 2, c = lane & 3;
#pragma unroll
    for (int kc = 0; kc < 4; kc++) {
        unsigned ah[2][4], al[2][4];
#pragma unroll
        for (int mt = 0; mt < 2; mt++) {
            int e = wb + mt * 16 + r;
            int k0 = kc * 16 + 2 * c;
            float2 v0 = *reinterpret_cast<const float2*>(&xs[(e + 0) * XST + k0]);
            float2 v1 = *reinterpret_cast<const float2*>(&xs[(e + 8) * XST + k0]);
            float2 v2 = *reinterpret_cast<const float2*>(&xs[(e + 0) * XST + k0 + 8]);
            float2 v3 = *reinterpret_cast<const float2*>(&xs[(e + 8) * XST + k0 + 8]);
            float2 t;
            ah[mt][0] = split_hi(v0, t); al[mt][0] = pack_h2(t.x, t.y);
            ah[mt][1] = split_hi(v1, t); al[mt][1] = pack_h2(t.x, t.y);
            ah[mt][2] = split_hi(v2, t); al[mt][2] = pack_h2(t.x, t.y);
            ah[mt][3] = split_hi(v3, t); al[mt][3] = pack_h2(t.x, t.y);
        }
#pragma unroll
        for (int nt = 0; nt < 8; nt++) {
            uint2 bh = whi[(kc * 8 + nt) * 32 + lane];
            uint2 bl = wlo[(kc * 8 + nt) * 32 + lane];
#pragma unroll
            for (int mt = 0; mt < 2; mt++) {
                mma_fp16(acc[mt][nt], ah[mt], bh);
                mma_fp16(acc[mt][nt], al[mt], bh);
                mma_fp16(acc[mt][nt], ah[mt], bl);
            }
        }
    }
}

// Generic tiled row-GEMM: out[r,:] = in[r,:] @ W + bias, guarded tail.
__device__ __forceinline__ void rowgemm_body(const float* __restrict__ in,
                                             const uint2* __restrict__ gWhi,
                                             const uint2* __restrict__ gWlo,
                                             const float* __restrict__ bias,
                                             float* __restrict__ out,
                                             int nrows) {
    extern __shared__ float sm[];
    float* xs = sm;                                          // [256][68]
    uint2* whi = reinterpret_cast<uint2*>(sm + TILE * XST);  // [1024]
    uint2* wlo = whi + 1024;                                 // [1024]
    float* bs = reinterpret_cast<float*>(wlo + 1024);        // [64]

    int t = threadIdx.x;
    int lane = t & 31;
    int wb = (t >> 5) * 32;
    int n0 = blockIdx.x * TILE;

    for (int i = t; i < 1024; i += 256) { whi[i] = gWhi[i]; wlo[i] = gWlo[i]; }
    if (t < BASIS) bs[t] = bias[t];

    const float4* in4 = reinterpret_cast<const float4*>(in);
    for (int i = t; i < TILE * 16; i += 256) {
        int e = i >> 4;
        float4 v = make_float4(0.f, 0.f, 0.f, 0.f);
        if (n0 + e < nrows) v = in4[(size_t)(n0 + e) * 16 + (i & 15)];
        *reinterpret_cast<float4*>(&xs[e * XST + ((i & 15) << 2)]) = v;
    }
    __syncthreads();

    float acc[2][8][4];
#pragma unroll
    for (int mt = 0; mt < 2; mt++)
#pragma unroll
        for (int nt = 0; nt < 8; nt++)
#pragma unroll
            for (int q = 0; q < 4; q++) acc[mt][nt][q] = 0.0f;

    mma_mainloop(xs, whi, wlo, wb, lane, acc);
    __syncthreads();   // reuse xs for output

    int r = lane >> 2, c = lane & 3;
#pragma unroll
    for (int mt = 0; mt < 2; mt++)
#pragma unroll
        for (int nt = 0; nt < 8; nt++) {
            int col = nt * 8 + 2 * c;
            int e = wb + mt * 16 + r;
            float b0 = bs[col], b1 = bs[col + 1];
            *reinterpret_cast<float2*>(&xs[e * XST + col]) =
                make_float2(acc[mt][nt][0] + b0, acc[mt][nt][1] + b1);
            *reinterpret_cast<float2*>(&xs[(e + 8) * XST + col]) =
                make_float2(acc[mt][nt][2] + b0, acc[mt][nt][3] + b1);
        }
    __syncthreads();

    float4* o4 = reinterpret_cast<float4*>(out);
    for (int i = t; i < TILE * 16; i += 256) {
        int e = i >> 4;
        if (n0 + e < nrows)
            o4[(size_t)(n0 + e) * 16 + (i & 15)] =
                *reinterpret_cast<const float4*>(&xs[e * XST + ((i & 15) << 2)]);
    }
}

// dfeat = edge_attr @ dfW + dfb
__global__ void __launch_bounds__(256, 2) k_dfeat(const float* __restrict__ in,
                                                  const float* __restrict__ bias,
                                                  float* __restrict__ out) {
    rowgemm_body(in, g_dfWhi, g_dfWlo, bias, out, NE);
}

// nf = C @ cfW + cfb  (tail-masked)
__global__ void __launch_bounds__(256, 2) k_nodemv(const float* __restrict__ C,
                                                   const float* __restrict__ bias,
                                                   float* __restrict__ out) {
    rowgemm_body(C, g_cfWhi, g_cfWlo, bias, out, NN);
}

// Edge kernel: C[dst] += tanh( (nf[src] * dfeat) @ fcW )  — in-place atomics
__global__ void __launch_bounds__(256, 2) k_edge(const float* __restrict__ nf,
                                                 const float* __restrict__ dfeat,
                                                 const int* __restrict__ src,
                                                 const int* __restrict__ dst,
                                                 float* __restrict__ Cout) {
    extern __shared__ float sm[];
    float* xs = sm;                                          // [256][68]
    uint2* whi = reinterpret_cast<uint2*>(sm + TILE * XST);  // [1024]
    uint2* wlo = whi + 1024;                                 // [1024]
    int* sIdx = reinterpret_cast<int*>(wlo + 1024);          // [256]
    int* dIdx = sIdx + TILE;                                 // [256]

    int t = threadIdx.x;
    int lane = t & 31;
    int wb = (t >> 5) * 32;
    size_t e0 = (size_t)blockIdx.x * TILE;

    for (int i = t; i < 1024; i += 256) { whi[i] = g_fcWhi[i]; wlo[i] = g_fcWlo[i]; }
    sIdx[t] = src[e0 + t];
    dIdx[t] = dst[e0 + t];
    __syncthreads();

    const float4* nf4 = reinterpret_cast<const float4*>(nf);
    const float4* df4 = reinterpret_cast<const float4*>(dfeat + e0 * BASIS);
    for (int i = t; i < TILE * 16; i += 256) {
        int e = i >> 4, k4 = i & 15;
        float4 a = nf4[(size_t)sIdx[e] * 16 + k4];
        float4 b = df4[i];
        *reinterpret_cast<float4*>(&xs[e * XST + (k4 << 2)]) =
            make_float4(a.x * b.x, a.y * b.y, a.z * b.z, a.w * b.w);
    }
    __syncthreads();

    float acc[2][8][4];
#pragma unroll
    for (int mt = 0; mt < 2; mt++)
#pragma unroll
        for (int nt = 0; nt < 8; nt++)
#pragma unroll
            for (int q = 0; q < 4; q++) acc[mt][nt][q] = 0.0f;

    mma_mainloop(xs, whi, wlo, wb, lane, acc);

    int r = lane >> 2, c = lane & 3;
#pragma unroll
    for (int mt = 0; mt < 2; mt++) {
        int eA = wb + mt * 16 + r;
        float* pA = Cout + (size_t)dIdx[eA] * BASIS;
        float* pB = Cout + (size_t)dIdx[eA + 8] * BASIS;
#pragma unroll
        for (int nt = 0; nt < 8; nt++) {
            float t0 = fast_tanh(acc[mt][nt][0]);
            float t1 = fast_tanh(acc[mt][nt][1]);
            float t2 = fast_tanh(acc[mt][nt][2]);
            float t3 = fast_tanh(acc[mt][nt][3]);
            float p0 = __shfl_xor_sync(0xffffffffu, t0, 1);
            float p1 = __shfl_xor_sync(0xffffffffu, t1, 1);
            float p2 = __shfl_xor_sync(0xffffffffu, t2, 1);
            float p3 = __shfl_xor_sync(0xffffffffu, t3, 1);
            if ((lane & 1) == 0) {
                int col = nt * 8 + 2 * c;   // c even here
                red_add_v4(pA + col, t0, t1, p0, p1);
                red_add_v4(pB + col, t2, t3, p2, p3);
            }
        }
    }
}

// Readout: h = tanh(C @ W1 + b1); o = h @ W2 + b2; out[batch[n]] += o
__global__ void __launch_bounds__(256) k_readout(const float* __restrict__ C,
                                                 const int* __restrict__ batch,
                                                 const float* __restrict__ W1,
                                                 const float* __restrict__ b1,
                                                 const float* __restrict__ W2,
                                                 const float* __restrict__ b2,
                                                 float* __restrict__ out) {
    __shared__ float W1s[BASIS * HID];
    __shared__ float W2s[HID * 4];
    __shared__ float b1s[HID];
    for (int i = threadIdx.x; i < BASIS * HID; i += blockDim.x) W1s[i] = W1[i];
    for (int i = threadIdx.x; i < HID * 4; i += blockDim.x) W2s[i] = W2[i];
    if (threadIdx.x < HID) b1s[threadIdx.x] = b1[threadIdx.x];
    __syncthreads();

    int n = blockIdx.x * blockDim.x + threadIdx.x;
    if (n >= NN) return;

    float x[BASIS];
    const float4* ip = reinterpret_cast<const float4*>(C + (size_t)n * BASIS);
#pragma unroll
    for (int i = 0; i < BASIS / 4; i++) {
        float4 v = ip[i];
        x[4 * i + 0] = v.x; x[4 * i + 1] = v.y;
        x[4 * i + 2] = v.z; x[4 * i + 3] = v.w;
    }

    float o0 = b2[0], o1 = b2[1], o2 = b2[2], o3 = b2[3];
#pragma unroll 1
    for (int j = 0; j < HID; j += 4) {
        float a0 = b1s[j + 0], a1 = b1s[j + 1], a2 = b1s[j + 2], a3 = b1s[j + 3];
#pragma unroll
        for (int k = 0; k < BASIS; k++) {
            float4 w = *reinterpret_cast<const float4*>(&W1s[k * HID + j]);
            a0 += x[k] * w.x; a1 += x[k] * w.y;
            a2 += x[k] * w.z; a3 += x[k] * w.w;
        }
        a0 = fast_tanh(a0); a1 = fast_tanh(a1);
        a2 = fast_tanh(a2); a3 = fast_tanh(a3);
        float4 r0 = *reinterpret_cast<const float4*>(&W2s[(j + 0) * 4]);
        float4 r1 = *reinterpret_cast<const float4*>(&W2s[(j + 1) * 4]);
        float4 r2 = *reinterpret_cast<const float4*>(&W2s[(j + 2) * 4]);
        float4 r3 = *reinterpret_cast<const float4*>(&W2s[(j + 3) * 4]);
        o0 += a0 * r0.x + a1 * r1.x + a2 * r2.x + a3 * r3.x;
        o1 += a0 * r0.y + a1 * r1.y + a2 * r2.y + a3 * r3.y;
        o2 += a0 * r0.z + a1 * r1.z + a2 * r2.z + a3 * r3.z;
        o3 += a0 * r0.w + a1 * r1.w + a2 * r2.w + a3 * r3.w;
    }
    red_add_v4(out + (size_t)batch[n] * 4, o0, o1, o2, o3);
}

extern "C" void kernel_launch(void* const* d_in, const int* in_sizes, int n_in,
                              void* d_out, int out_size) {
    const int*   Z         = (const int*)d_in[0];
    const int*   ei        = (const int*)d_in[1];
    const float* edge_attr = (const float*)d_in[2];
    const int*   batch     = (const int*)d_in[3];
    const float* embed     = (const float*)d_in[4];
    const float* cfW       = (const float*)d_in[5];
    const float* cfb       = (const float*)d_in[6];
    const float* dfW       = (const float*)d_in[7];
    const float* dfb       = (const float*)d_in[8];
    const float* fcW       = (const float*)d_in[9];
    const float* W1        = (const float*)d_in[10];
    const float* b1        = (const float*)d_in[11];
    const float* W2        = (const float*)d_in[12];
    const float* b2        = (const float*)d_in[13];
    const int* src = ei;
    const int* dst = ei + NE;

    float *Ca, *nf, *dfeat;
    cudaGetSymbolAddress((void**)&Ca, g_Ca);
    cudaGetSymbolAddress((void**)&nf, g_nf);
    cudaGetSymbolAddress((void**)&dfeat, g_dfeat);

    const int SM_GEMM = TILE * XST * 4 + 2 * 1024 * 8 + 64 * 4;        // 86272
    const int SM_EDGE = TILE * XST * 4 + 2 * 1024 * 8 + 2 * TILE * 4;  // 88064
    cudaFuncSetAttribute(k_dfeat, cudaFuncAttributeMaxDynamicSharedMemorySize, SM_GEMM);
    cudaFuncSetAttribute(k_nodemv, cudaFuncAttributeMaxDynamicSharedMemorySize, SM_GEMM);
    cudaFuncSetAttribute(k_edge, cudaFuncAttributeMaxDynamicSharedMemorySize, SM_EDGE);

    k_prep<<<1, 256>>>(fcW, dfW, cfW);
    k_init_C<<<(NN * BASIS + 255) / 256, 256>>>(Z, embed, Ca);
    k_dfeat<<<NE / TILE, 256, SM_GEMM>>>(edge_attr, dfb, dfeat);

    for (int t = 0; t < 3; t++) {
        k_nodemv<<<(NN + TILE - 1) / TILE, 256, SM_GEMM>>>(Ca, cfb, nf);
        k_edge<<<NE / TILE, 256, SM_EDGE>>>(nf, dfeat, src, dst, Ca);
    }

    k_zero<<<(NG * 4 + 255) / 256, 256>>>((float*)d_out, NG * 4);
    k_readout<<<(NN + 255) / 256, 256>>>(Ca, batch, W1, b1, W2, b2, (float*)d_out);
}

// round 5
// speedup vs baseline: 2.8388x; 1.5402x over previous
#include <cuda_runtime.h>
#include <cuda_fp16.h>
#include <cstdint>
#include <cstddef>

#define NN 50000
#define NE 800000
#define BASIS 64
#define HID 128
#define NG 512
#define TILE 256
#define XST 68          // smem stride (floats) for staged tiles

// Scratch (__device__ globals per allocation rules).
__device__ __align__(256) float g_dfeat[(size_t)NE * BASIS];
__device__ __align__(256) float g_nf[(size_t)NN * BASIS];
__device__ __align__(256) float g_Ca[(size_t)NN * BASIS];
// fp16 hi/lo B-fragment tables: [kc 4][nt 8][lane 32] -> uint2 (4 half each)
__device__ __align__(256) uint2 g_fcWhi[1024];
__device__ __align__(256) uint2 g_fcWlo[1024];
__device__ __align__(256) uint2 g_dfWhi[1024];
__device__ __align__(256) uint2 g_dfWlo[1024];
__device__ __align__(256) uint2 g_cfWhi[1024];
__device__ __align__(256) uint2 g_cfWlo[1024];

__device__ __forceinline__ float fast_tanh(float v) {
    float y;
    asm("tanh.approx.f32 %0, %1;" : "=f"(y) : "f"(v));
    return y;
}
__device__ __forceinline__ void red_add_v4(float* p, float a, float b, float c, float d) {
    asm volatile("red.global.add.v4.f32 [%0], {%1, %2, %3, %4};"
                 :: "l"(p), "f"(a), "f"(b), "f"(c), "f"(d) : "memory");
}
__device__ __forceinline__ unsigned pack_h2(float x, float y) {
    __half2 h = __floats2half2_rn(x, y);
    return *reinterpret_cast<unsigned*>(&h);
}
__device__ __forceinline__ unsigned split_hi(float2 v, float2& rest) {
    __half2 h = __floats2half2_rn(v.x, v.y);
    rest.x = v.x - __low2float(h);
    rest.y = v.y - __high2float(h);
    return *reinterpret_cast<unsigned*>(&h);
}
__device__ __forceinline__ void mma_fp16(float* d, const unsigned* a, const uint2 b) {
    asm volatile(
        "mma.sync.aligned.m16n8k16.row.col.f32.f16.f16.f32 "
        "{%0,%1,%2,%3}, {%4,%5,%6,%7}, {%8,%9}, {%0,%1,%2,%3};"
        : "+f"(d[0]), "+f"(d[1]), "+f"(d[2]), "+f"(d[3])
        : "r"(a[0]), "r"(a[1]), "r"(a[2]), "r"(a[3]),
          "r"(b.x), "r"(b.y));
}

// Build permuted fp16 hi/lo B-fragment tables for 64x64 weights (out = x @ W).
__global__ void __launch_bounds__(256) k_prep(const float* __restrict__ fcW,
                                              const float* __restrict__ dfW,
                                              const float* __restrict__ cfW) {
    for (int idx = threadIdx.x; idx < 1024; idx += 256) {
        int kc = idx >> 8;
        int nt = (idx >> 5) & 7;
        int lane = idx & 31;
        int n = nt * 8 + (lane >> 2);
        int k0 = kc * 16 + (lane & 3) * 2;
        const float* Ws[3] = {fcW, dfW, cfW};
        uint2* hiT[3] = {g_fcWhi, g_dfWhi, g_cfWhi};
        uint2* loT[3] = {g_fcWlo, g_dfWlo, g_cfWlo};
#pragma unroll
        for (int w = 0; w < 3; w++) {
            float w00 = Ws[w][(k0 + 0) * BASIS + n];
            float w01 = Ws[w][(k0 + 1) * BASIS + n];
            float w10 = Ws[w][(k0 + 8) * BASIS + n];
            float w11 = Ws[w][(k0 + 9) * BASIS + n];
            float2 r0, r1;
            uint2 hi, lo;
            hi.x = split_hi(make_float2(w00, w01), r0);
            hi.y = split_hi(make_float2(w10, w11), r1);
            lo.x = pack_h2(r0.x, r0.y);
            lo.y = pack_h2(r1.x, r1.y);
            hiT[w][idx] = hi;
            loT[w][idx] = lo;
        }
    }
}

__global__ void __launch_bounds__(256) k_init_C(const int* __restrict__ Z,
                                                const float* __restrict__ embed,
                                                float* __restrict__ C) {
    int idx = blockIdx.x * blockDim.x + threadIdx.x;
    if (idx >= NN * BASIS) return;
    C[idx] = embed[Z[idx >> 6] * BASIS + (idx & 63)];
}

__global__ void __launch_bounds__(256) k_zero(float* __restrict__ p, int n) {
    int i = blockIdx.x * blockDim.x + threadIdx.x;
    if (i < n) p[i] = 0.0f;
}

// ---------------------------------------------------------------------------
// fp16-split mainloop: acc[mt][nt][4] += xs-tile @ W (3-product Markidis).
// Warp-local: warp owns rows [wb, wb+32) of xs.
// ---------------------------------------------------------------------------
__device__ __forceinline__ void mma_mainloop(const float* __restrict__ xs,
                                             const uint2* __restrict__ whi,
                                             const uint2* __restrict__ wlo,
                                             int wb, int lane,
                                             float acc[2][8][4]) {
    int r = lane >> 2, c = lane & 3;
#pragma unroll
    for (int kc = 0; kc < 4; kc++) {
        unsigned ah[2][4], al[2][4];
#pragma unroll
        for (int mt = 0; mt < 2; mt++) {
            int e = wb + mt * 16 + r;
            int k0 = kc * 16 + 2 * c;
            float2 v0 = *reinterpret_cast<const float2*>(&xs[(e + 0) * XST + k0]);
            float2 v1 = *reinterpret_cast<const float2*>(&xs[(e + 8) * XST + k0]);
            float2 v2 = *reinterpret_cast<const float2*>(&xs[(e + 0) * XST + k0 + 8]);
            float2 v3 = *reinterpret_cast<const float2*>(&xs[(e + 8) * XST + k0 + 8]);
            float2 t;
            ah[mt][0] = split_hi(v0, t); al[mt][0] = pack_h2(t.x, t.y);
            ah[mt][1] = split_hi(v1, t); al[mt][1] = pack_h2(t.x, t.y);
            ah[mt][2] = split_hi(v2, t); al[mt][2] = pack_h2(t.x, t.y);
            ah[mt][3] = split_hi(v3, t); al[mt][3] = pack_h2(t.x, t.y);
        }
#pragma unroll
        for (int nt = 0; nt < 8; nt++) {
            uint2 bh = whi[(kc * 8 + nt) * 32 + lane];
            uint2 bl = wlo[(kc * 8 + nt) * 32 + lane];
#pragma unroll
            for (int mt = 0; mt < 2; mt++) {
                mma_fp16(acc[mt][nt], ah[mt], bh);
                mma_fp16(acc[mt][nt], al[mt], bh);
                mma_fp16(acc[mt][nt], ah[mt], bl);
            }
        }
    }
}

// Generic tiled row-GEMM, warp-autonomous tiles: out = in @ W + bias.
__device__ __forceinline__ void rowgemm_body(const float* __restrict__ in,
                                             const uint2* __restrict__ gWhi,
                                             const uint2* __restrict__ gWlo,
                                             const float* __restrict__ bias,
                                             float* __restrict__ out,
                                             int nrows) {
    extern __shared__ float sm[];
    float* xs = sm;                                          // [256][68]
    uint2* whi = reinterpret_cast<uint2*>(sm + TILE * XST);  // [1024]
    uint2* wlo = whi + 1024;                                 // [1024]
    float* bs = reinterpret_cast<float*>(wlo + 1024);        // [64]

    int t = threadIdx.x;
    int lane = t & 31;
    int wb = (t >> 5) * 32;
    int n0 = blockIdx.x * TILE;

    for (int i = t; i < 1024; i += 256) { whi[i] = gWhi[i]; wlo[i] = gWlo[i]; }
    if (t < BASIS) bs[t] = bias[t];
    __syncthreads();   // tables ready; everything below is warp-local

    const float4* in4 = reinterpret_cast<const float4*>(in);
#pragma unroll
    for (int it = 0; it < 16; it++) {
        int j = it * 32 + lane;
        int e = wb + (j >> 4);
        int k4 = j & 15;
        float4 v = make_float4(0.f, 0.f, 0.f, 0.f);
        if (n0 + e < nrows) v = in4[(size_t)(n0 + e) * 16 + k4];
        *reinterpret_cast<float4*>(&xs[e * XST + (k4 << 2)]) = v;
    }
    __syncwarp();

    float acc[2][8][4];
#pragma unroll
    for (int mt = 0; mt < 2; mt++)
#pragma unroll
        for (int nt = 0; nt < 8; nt++)
#pragma unroll
            for (int q = 0; q < 4; q++) acc[mt][nt][q] = 0.0f;

    mma_mainloop(xs, whi, wlo, wb, lane, acc);
    __syncwarp();   // xs reuse (warp-local region only)

    int r = lane >> 2, c = lane & 3;
#pragma unroll
    for (int mt = 0; mt < 2; mt++)
#pragma unroll
        for (int nt = 0; nt < 8; nt++) {
            int col = nt * 8 + 2 * c;
            int e = wb + mt * 16 + r;
            float b0 = bs[col], b1 = bs[col + 1];
            *reinterpret_cast<float2*>(&xs[e * XST + col]) =
                make_float2(acc[mt][nt][0] + b0, acc[mt][nt][1] + b1);
            *reinterpret_cast<float2*>(&xs[(e + 8) * XST + col]) =
                make_float2(acc[mt][nt][2] + b0, acc[mt][nt][3] + b1);
        }
    __syncwarp();

    float4* o4 = reinterpret_cast<float4*>(out);
#pragma unroll
    for (int it = 0; it < 16; it++) {
        int j = it * 32 + lane;
        int e = wb + (j >> 4);
        int k4 = j & 15;
        if (n0 + e < nrows)
            o4[(size_t)(n0 + e) * 16 + k4] =
                *reinterpret_cast<const float4*>(&xs[e * XST + (k4 << 2)]);
    }
}

// dfeat = edge_attr @ dfW + dfb
__global__ void __launch_bounds__(256, 2) k_dfeat(const float* __restrict__ in,
                                                  const float* __restrict__ bias,
                                                  float* __restrict__ out) {
    rowgemm_body(in, g_dfWhi, g_dfWlo, bias, out, NE);
}

// nf = C @ cfW + cfb  (tail-masked)
__global__ void __launch_bounds__(256, 2) k_nodemv(const float* __restrict__ C,
                                                   const float* __restrict__ bias,
                                                   float* __restrict__ out) {
    rowgemm_body(C, g_cfWhi, g_cfWlo, bias, out, NN);
}

// Edge kernel: C[dst] += tanh( (nf[src] * dfeat) @ fcW ) — warp-autonomous
__global__ void __launch_bounds__(256, 2) k_edge(const float* __restrict__ nf,
                                                 const float* __restrict__ dfeat,
                                                 const int* __restrict__ src,
                                                 const int* __restrict__ dst,
                                                 float* __restrict__ Cout) {
    extern __shared__ float sm[];
    float* xs = sm;                                          // [256][68]
    uint2* whi = reinterpret_cast<uint2*>(sm + TILE * XST);  // [1024]
    uint2* wlo = whi + 1024;                                 // [1024]

    int t = threadIdx.x;
    int lane = t & 31;
    int wb = (t >> 5) * 32;
    size_t e0 = (size_t)blockIdx.x * TILE;

    for (int i = t; i < 1024; i += 256) { whi[i] = g_fcWhi[i]; wlo[i] = g_fcWlo[i]; }

    // Per-lane edge indices for this warp's 32 rows (register-resident, shfl'd)
    int sval = src[e0 + wb + lane];
    int dval = dst[e0 + wb + lane];

    __syncthreads();   // tables ready; everything below is warp-local

    const float4* nf4 = reinterpret_cast<const float4*>(nf);
    const float4* df4 = reinterpret_cast<const float4*>(dfeat + e0 * BASIS);
#pragma unroll
    for (int it = 0; it < 16; it++) {
        int j = it * 32 + lane;
        int er = j >> 4;                 // row within warp tile: 2*it .. 2*it+1
        int k4 = j & 15;
        int s = __shfl_sync(0xffffffffu, sval, er);
        int e = wb + er;
        float4 a = nf4[(size_t)s * 16 + k4];
        float4 b = df4[(size_t)e * 16 + k4];
        *reinterpret_cast<float4*>(&xs[e * XST + (k4 << 2)]) =
            make_float4(a.x * b.x, a.y * b.y, a.z * b.z, a.w * b.w);
    }
    __syncwarp();

    float acc[2][8][4];
#pragma unroll
    for (int mt = 0; mt < 2; mt++)
#pragma unroll
        for (int nt = 0; nt < 8; nt++)
#pragma unroll
            for (int q = 0; q < 4; q++) acc[mt][nt][q] = 0.0f;

    mma_mainloop(xs, whi, wlo, wb, lane, acc);

    int r = lane >> 2, c = lane & 3;
#pragma unroll
    for (int mt = 0; mt < 2; mt++) {
        int dA = __shfl_sync(0xffffffffu, dval, mt * 16 + r);
        int dB = __shfl_sync(0xffffffffu, dval, mt * 16 + r + 8);
        float* pA = Cout + (size_t)dA * BASIS;
        float* pB = Cout + (size_t)dB * BASIS;
#pragma unroll
        for (int nt = 0; nt < 8; nt++) {
            float t0 = fast_tanh(acc[mt][nt][0]);
            float t1 = fast_tanh(acc[mt][nt][1]);
            float t2 = fast_tanh(acc[mt][nt][2]);
            float t3 = fast_tanh(acc[mt][nt][3]);
            float p0 = __shfl_xor_sync(0xffffffffu, t0, 1);
            float p1 = __shfl_xor_sync(0xffffffffu, t1, 1);
            float p2 = __shfl_xor_sync(0xffffffffu, t2, 1);
            float p3 = __shfl_xor_sync(0xffffffffu, t3, 1);
            if ((lane & 1) == 0) {
                int col = nt * 8 + 2 * c;   // c even here
                red_add_v4(pA + col, t0, t1, p0, p1);
                red_add_v4(pB + col, t2, t3, p2, p3);
            }
        }
    }
}

// Readout: h = tanh(C @ W1 + b1); o = h @ W2 + b2; out[batch[n]] += o
__global__ void __launch_bounds__(256) k_readout(const float* __restrict__ C,
                                                 const int* __restrict__ batch,
                                                 const float* __restrict__ W1,
                                                 const float* __restrict__ b1,
                                                 const float* __restrict__ W2,
                                                 const float* __restrict__ b2,
                                                 float* __restrict__ out) {
    __shared__ float W1s[BASIS * HID];
    __shared__ float W2s[HID * 4];
    __shared__ float b1s[HID];
    for (int i = threadIdx.x; i < BASIS * HID; i += blockDim.x) W1s[i] = W1[i];
    for (int i = threadIdx.x; i < HID * 4; i += blockDim.x) W2s[i] = W2[i];
    if (threadIdx.x < HID) b1s[threadIdx.x] = b1[threadIdx.x];
    __syncthreads();

    int n = blockIdx.x * blockDim.x + threadIdx.x;
    if (n >= NN) return;

    float x[BASIS];
    const float4* ip = reinterpret_cast<const float4*>(C + (size_t)n * BASIS);
#pragma unroll
    for (int i = 0; i < BASIS / 4; i++) {
        float4 v = ip[i];
        x[4 * i + 0] = v.x; x[4 * i + 1] = v.y;
        x[4 * i + 2] = v.z; x[4 * i + 3] = v.w;
    }

    float o0 = b2[0], o1 = b2[1], o2 = b2[2], o3 = b2[3];
#pragma unroll 1
    for (int j = 0; j < HID; j += 4) {
        float a0 = b1s[j + 0], a1 = b1s[j + 1], a2 = b1s[j + 2], a3 = b1s[j + 3];
#pragma unroll
        for (int k = 0; k < BASIS; k++) {
            float4 w = *reinterpret_cast<const float4*>(&W1s[k * HID + j]);
            a0 += x[k] * w.x; a1 += x[k] * w.y;
            a2 += x[k] * w.z; a3 += x[k] * w.w;
        }
        a0 = fast_tanh(a0); a1 = fast_tanh(a1);
        a2 = fast_tanh(a2); a3 = fast_tanh(a3);
        float4 r0 = *reinterpret_cast<const float4*>(&W2s[(j + 0) * 4]);
        float4 r1 = *reinterpret_cast<const float4*>(&W2s[(j + 1) * 4]);
        float4 r2 = *reinterpret_cast<const float4*>(&W2s[(j + 2) * 4]);
        float4 r3 = *reinterpret_cast<const float4*>(&W2s[(j + 3) * 4]);
        o0 += a0 * r0.x + a1 * r1.x + a2 * r2.x + a3 * r3.x;
        o1 += a0 * r0.y + a1 * r1.y + a2 * r2.y + a3 * r3.y;
        o2 += a0 * r0.z + a1 * r1.z + a2 * r2.z + a3 * r3.z;
        o3 += a0 * r0.w + a1 * r1.w + a2 * r2.w + a3 * r3.w;
    }
    red_add_v4(out + (size_t)batch[n] * 4, o0, o1, o2, o3);
}

extern "C" void kernel_launch(void* const* d_in, const int* in_sizes, int n_in,
                              void* d_out, int out_size) {
    const int*   Z         = (const int*)d_in[0];
    const int*   ei        = (const int*)d_in[1];
    const float* edge_attr = (const float*)d_in[2];
    const int*   batch     = (const int*)d_in[3];
    const float* embed     = (const float*)d_in[4];
    const float* cfW       = (const float*)d_in[5];
    const float* cfb       = (const float*)d_in[6];
    const float* dfW       = (const float*)d_in[7];
    const float* dfb       = (const float*)d_in[8];
    const float* fcW       = (const float*)d_in[9];
    const float* W1        = (const float*)d_in[10];
    const float* b1        = (const float*)d_in[11];
    const float* W2        = (const float*)d_in[12];
    const float* b2        = (const float*)d_in[13];
    const int* src = ei;
    const int* dst = ei + NE;

    float *Ca, *nf, *dfeat;
    cudaGetSymbolAddress((void**)&Ca, g_Ca);
    cudaGetSymbolAddress((void**)&nf, g_nf);
    cudaGetSymbolAddress((void**)&dfeat, g_dfeat);

    const int SM_GEMM = TILE * XST * 4 + 2 * 1024 * 8 + 64 * 4;   // 86272
    const int SM_EDGE = TILE * XST * 4 + 2 * 1024 * 8;            // 86016
    cudaFuncSetAttribute(k_dfeat, cudaFuncAttributeMaxDynamicSharedMemorySize, SM_GEMM);
    cudaFuncSetAttribute(k_nodemv, cudaFuncAttributeMaxDynamicSharedMemorySize, SM_GEMM);
    cudaFuncSetAttribute(k_edge, cudaFuncAttributeMaxDynamicSharedMemorySize, SM_EDGE);

    k_prep<<<1, 256>>>(fcW, dfW, cfW);
    k_init_C<<<(NN * BASIS + 255) / 256, 256>>>(Z, embed, Ca);
    k_dfeat<<<NE / TILE, 256, SM_GEMM>>>(edge_attr, dfb, dfeat);

    for (int t = 0; t < 3; t++) {
        k_nodemv<<<(NN + TILE - 1) / TILE, 256, SM_GEMM>>>(Ca, cfb, nf);
        k_edge<<<NE / TILE, 256, SM_EDGE>>>(nf, dfeat, src, dst, Ca);
    }

    k_zero<<<(NG * 4 + 255) / 256, 256>>>((float*)d_out, NG * 4);
    k_readout<<<(NN + 255) / 256, 256>>>(Ca, batch, W1, b1, W2, b2, (float*)d_out);
}

// round 6
// speedup vs baseline: 3.1501x; 1.1097x over previous
#include <cuda_runtime.h>
#include <cuda_fp16.h>
#include <cstdint>
#include <cstddef>

#define NN 50000
#define NE 800000
#define BASIS 64
#define HID 128
#define NG 512
#define TILE 256
#define XST 68          // smem stride (floats) for staged tiles
#define GRID 296        // persistent: 2 blocks per SM (148 SMs)

// Scratch (__device__ globals per allocation rules).
__device__ __align__(256) float g_dfeat[(size_t)NE * BASIS];
__device__ __align__(256) float g_nf[(size_t)NN * BASIS];
__device__ __align__(256) float g_Ca[(size_t)NN * BASIS];
// fp16 hi/lo B-fragment tables: [kc 4][nt 8][lane 32] -> uint2 (4 half each)
__device__ __align__(256) uint2 g_fcWhi[1024];
__device__ __align__(256) uint2 g_fcWlo[1024];
__device__ __align__(256) uint2 g_dfWhi[1024];
__device__ __align__(256) uint2 g_dfWlo[1024];
__device__ __align__(256) uint2 g_cfWhi[1024];
__device__ __align__(256) uint2 g_cfWlo[1024];
// W1 (64x128) as two 64x64 halves: [half 2][1024]
__device__ __align__(256) uint2 g_W1hi[2048];
__device__ __align__(256) uint2 g_W1lo[2048];

__device__ __forceinline__ float fast_tanh(float v) {
    float y;
    asm("tanh.approx.f32 %0, %1;" : "=f"(y) : "f"(v));
    return y;
}
__device__ __forceinline__ void red_add_v4(float* p, float a, float b, float c, float d) {
    asm volatile("red.global.add.v4.f32 [%0], {%1, %2, %3, %4};"
                 :: "l"(p), "f"(a), "f"(b), "f"(c), "f"(d) : "memory");
}
__device__ __forceinline__ unsigned pack_h2(float x, float y) {
    __half2 h = __floats2half2_rn(x, y);
    return *reinterpret_cast<unsigned*>(&h);
}
__device__ __forceinline__ unsigned split_hi(float2 v, float2& rest) {
    __half2 h = __floats2half2_rn(v.x, v.y);
    rest.x = v.x - __low2float(h);
    rest.y = v.y - __high2float(h);
    return *reinterpret_cast<unsigned*>(&h);
}
__device__ __forceinline__ void mma_fp16(float* d, const unsigned* a, const uint2 b) {
    asm volatile(
        "mma.sync.aligned.m16n8k16.row.col.f32.f16.f16.f32 "
        "{%0,%1,%2,%3}, {%4,%5,%6,%7}, {%8,%9}, {%0,%1,%2,%3};"
        : "+f"(d[0]), "+f"(d[1]), "+f"(d[2]), "+f"(d[3])
        : "r"(a[0]), "r"(a[1]), "r"(a[2]), "r"(a[3]),
          "r"(b.x), "r"(b.y));
}

// Build permuted fp16 hi/lo B-fragment tables (out = x @ W).
__global__ void __launch_bounds__(256) k_prep(const float* __restrict__ fcW,
                                              const float* __restrict__ dfW,
                                              const float* __restrict__ cfW,
                                              const float* __restrict__ W1) {
    for (int idx = threadIdx.x; idx < 1024; idx += 256) {
        int kc = idx >> 8;
        int nt = (idx >> 5) & 7;
        int lane = idx & 31;
        int n = nt * 8 + (lane >> 2);
        int k0 = kc * 16 + (lane & 3) * 2;
        const float* Ws[3] = {fcW, dfW, cfW};
        uint2* hiT[3] = {g_fcWhi, g_dfWhi, g_cfWhi};
        uint2* loT[3] = {g_fcWlo, g_dfWlo, g_cfWlo};
#pragma unroll
        for (int w = 0; w < 3; w++) {
            float w00 = Ws[w][(k0 + 0) * BASIS + n];
            float w01 = Ws[w][(k0 + 1) * BASIS + n];
            float w10 = Ws[w][(k0 + 8) * BASIS + n];
            float w11 = Ws[w][(k0 + 9) * BASIS + n];
            float2 r0, r1;
            uint2 hi, lo;
            hi.x = split_hi(make_float2(w00, w01), r0);
            hi.y = split_hi(make_float2(w10, w11), r1);
            lo.x = pack_h2(r0.x, r0.y);
            lo.y = pack_h2(r1.x, r1.y);
            hiT[w][idx] = hi;
            loT[w][idx] = lo;
        }
    }
    // W1 tables (two 64-col halves)
    for (int idx = threadIdx.x; idx < 2048; idx += 256) {
        int hf = idx >> 10;
        int rest = idx & 1023;
        int kc = rest >> 8;
        int nt = (rest >> 5) & 7;
        int lane = rest & 31;
        int n = hf * 64 + nt * 8 + (lane >> 2);
        int k0 = kc * 16 + (lane & 3) * 2;
        float w00 = W1[(k0 + 0) * HID + n];
        float w01 = W1[(k0 + 1) * HID + n];
        float w10 = W1[(k0 + 8) * HID + n];
        float w11 = W1[(k0 + 9) * HID + n];
        float2 r0, r1;
        uint2 hi, lo;
        hi.x = split_hi(make_float2(w00, w01), r0);
        hi.y = split_hi(make_float2(w10, w11), r1);
        lo.x = pack_h2(r0.x, r0.y);
        lo.y = pack_h2(r1.x, r1.y);
        g_W1hi[idx] = hi;
        g_W1lo[idx] = lo;
    }
}

__global__ void __launch_bounds__(256) k_init_C(const int* __restrict__ Z,
                                                const float* __restrict__ embed,
                                                float* __restrict__ C) {
    int idx = blockIdx.x * blockDim.x + threadIdx.x;
    if (idx >= NN * BASIS) return;
    C[idx] = embed[Z[idx >> 6] * BASIS + (idx & 63)];
}

__global__ void __launch_bounds__(256) k_zero(float* __restrict__ p, int n) {
    int i = blockIdx.x * blockDim.x + threadIdx.x;
    if (i < n) p[i] = 0.0f;
}

// ---------------------------------------------------------------------------
// fp16-split mainloop: acc[mt][nt][4] += xs-tile @ W (3-product Markidis).
// Warp-local: warp owns xs rows [wb, wb+32).
// ---------------------------------------------------------------------------
__device__ __forceinline__ void mma_mainloop(const float* __restrict__ xs,
                                             const uint2* __restrict__ whi,
                                             const uint2* __restrict__ wlo,
                                             int wb, int lane,
                                             float acc[2][8][4]) {
    int r = lane >> 2, c = lane & 3;
#pragma unroll
    for (int kc = 0; kc < 4; kc++) {
        unsigned ah[2][4], al[2][4];
#pragma unroll
        for (int mt = 0; mt < 2; mt++) {
            int e = wb + mt * 16 + r;
            int k0 = kc * 16 + 2 * c;
            float2 v0 = *reinterpret_cast<const float2*>(&xs[(e + 0) * XST + k0]);
            float2 v1 = *reinterpret_cast<const float2*>(&xs[(e + 8) * XST + k0]);
            float2 v2 = *reinterpret_cast<const float2*>(&xs[(e + 0) * XST + k0 + 8]);
            float2 v3 = *reinterpret_cast<const float2*>(&xs[(e + 8) * XST + k0 + 8]);
            float2 t;
            ah[mt][0] = split_hi(v0, t); al[mt][0] = pack_h2(t.x, t.y);
            ah[mt][1] = split_hi(v1, t); al[mt][1] = pack_h2(t.x, t.y);
            ah[mt][2] = split_hi(v2, t); al[mt][2] = pack_h2(t.x, t.y);
            ah[mt][3] = split_hi(v3, t); al[mt][3] = pack_h2(t.x, t.y);
        }
#pragma unroll
        for (int nt = 0; nt < 8; nt++) {
            uint2 bh = whi[(kc * 8 + nt) * 32 + lane];
            uint2 bl = wlo[(kc * 8 + nt) * 32 + lane];
#pragma unroll
            for (int mt = 0; mt < 2; mt++) {
                mma_fp16(acc[mt][nt], ah[mt], bh);
                mma_fp16(acc[mt][nt], al[mt], bh);
                mma_fp16(acc[mt][nt], ah[mt], bl);
            }
        }
    }
}

#define ZERO_ACC(acc)                                   \
    _Pragma("unroll")                                   \
    for (int mt = 0; mt < 2; mt++)                      \
        _Pragma("unroll")                               \
        for (int nt = 0; nt < 8; nt++)                  \
            _Pragma("unroll")                           \
            for (int q = 0; q < 4; q++) acc[mt][nt][q] = 0.0f;

// Persistent tiled row-GEMM: out = in @ W + bias. Warp-tiles of 32 rows.
__device__ __forceinline__ void rowgemm_body(const float* __restrict__ in,
                                             const uint2* __restrict__ gWhi,
                                             const uint2* __restrict__ gWlo,
                                             const float* __restrict__ bias,
                                             float* __restrict__ out,
                                             int nrows) {
    extern __shared__ float sm[];
    float* xs = sm;                                          // [256][68]
    uint2* whi = reinterpret_cast<uint2*>(sm + TILE * XST);  // [1024]
    uint2* wlo = whi + 1024;                                 // [1024]
    float* bs = reinterpret_cast<float*>(wlo + 1024);        // [64]

    int t = threadIdx.x;
    int lane = t & 31;
    int wb = (t >> 5) * 32;

    for (int i = t; i < 1024; i += 256) { whi[i] = gWhi[i]; wlo[i] = gWlo[i]; }
    if (t < BASIS) bs[t] = bias[t];
    __syncthreads();   // tables ready; everything below is warp-local

    int warpId = blockIdx.x * 8 + (t >> 5);
    const int NWP = GRID * 8;
    int tiles = (nrows + 31) / 32;
    const float4* in4 = reinterpret_cast<const float4*>(in);
    float4* o4 = reinterpret_cast<float4*>(out);
    int r = lane >> 2, c = lane & 3;

    for (int wt = warpId; wt < tiles; wt += NWP) {
        int n0 = wt * 32;
        __syncwarp();
#pragma unroll
        for (int it = 0; it < 16; it++) {
            int j = it * 32 + lane;
            int e = j >> 4;
            int k4 = j & 15;
            float4 v = make_float4(0.f, 0.f, 0.f, 0.f);
            if (n0 + e < nrows) v = in4[(size_t)(n0 + e) * 16 + k4];
            *reinterpret_cast<float4*>(&xs[(wb + e) * XST + (k4 << 2)]) = v;
        }
        __syncwarp();

        float acc[2][8][4];
        ZERO_ACC(acc)
        mma_mainloop(xs, whi, wlo, wb, lane, acc);
        __syncwarp();   // xs reuse

#pragma unroll
        for (int mt = 0; mt < 2; mt++)
#pragma unroll
            for (int nt = 0; nt < 8; nt++) {
                int col = nt * 8 + 2 * c;
                int e = wb + mt * 16 + r;
                float b0 = bs[col], b1 = bs[col + 1];
                *reinterpret_cast<float2*>(&xs[e * XST + col]) =
                    make_float2(acc[mt][nt][0] + b0, acc[mt][nt][1] + b1);
                *reinterpret_cast<float2*>(&xs[(e + 8) * XST + col]) =
                    make_float2(acc[mt][nt][2] + b0, acc[mt][nt][3] + b1);
            }
        __syncwarp();

#pragma unroll
        for (int it = 0; it < 16; it++) {
            int j = it * 32 + lane;
            int e = j >> 4;
            int k4 = j & 15;
            if (n0 + e < nrows)
                o4[(size_t)(n0 + e) * 16 + k4] =
                    *reinterpret_cast<const float4*>(&xs[(wb + e) * XST + (k4 << 2)]);
        }
    }
}

__global__ void __launch_bounds__(256, 2) k_dfeat(const float* __restrict__ in,
                                                  const float* __restrict__ bias,
                                                  float* __restrict__ out) {
    rowgemm_body(in, g_dfWhi, g_dfWlo, bias, out, NE);
}

__global__ void __launch_bounds__(256, 2) k_nodemv(const float* __restrict__ C,
                                                   const float* __restrict__ bias,
                                                   float* __restrict__ out) {
    rowgemm_body(C, g_cfWhi, g_cfWlo, bias, out, NN);
}

// Edge kernel: C[dst] += tanh( (nf[src] * dfeat) @ fcW ) — persistent warps
__global__ void __launch_bounds__(256, 2) k_edge(const float* __restrict__ nf,
                                                 const float* __restrict__ dfeat,
                                                 const int* __restrict__ src,
                                                 const int* __restrict__ dst,
                                                 float* __restrict__ Cout) {
    extern __shared__ float sm[];
    float* xs = sm;                                          // [256][68]
    uint2* whi = reinterpret_cast<uint2*>(sm + TILE * XST);  // [1024]
    uint2* wlo = whi + 1024;                                 // [1024]

    int t = threadIdx.x;
    int lane = t & 31;
    int wb = (t >> 5) * 32;

    for (int i = t; i < 1024; i += 256) { whi[i] = g_fcWhi[i]; wlo[i] = g_fcWlo[i]; }
    __syncthreads();   // tables ready; everything below is warp-local

    int warpId = blockIdx.x * 8 + (t >> 5);
    const int NWP = GRID * 8;
    const int tiles = NE / 32;   // 25000 exact
    const float4* nf4 = reinterpret_cast<const float4*>(nf);
    const float4* df4 = reinterpret_cast<const float4*>(dfeat);
    int r = lane >> 2, c = lane & 3;

    int wt = warpId;
    int sval = 0, dval = 0;
    if (wt < tiles) {
        sval = src[(size_t)wt * 32 + lane];
        dval = dst[(size_t)wt * 32 + lane];
    }
    for (; wt < tiles; wt += NWP) {
        // prefetch next tile's indices
        int wn = wt + NWP;
        int sv_n = 0, dv_n = 0;
        if (wn < tiles) {
            sv_n = src[(size_t)wn * 32 + lane];
            dv_n = dst[(size_t)wn * 32 + lane];
        }
        __syncwarp();   // previous mainloop reads done before restage
#pragma unroll
        for (int it = 0; it < 16; it++) {
            int j = it * 32 + lane;
            int er = j >> 4;
            int k4 = j & 15;
            int s = __shfl_sync(0xffffffffu, sval, er);
            float4 a = nf4[(size_t)s * 16 + k4];
            float4 b = df4[((size_t)wt * 32 + er) * 16 + k4];
            *reinterpret_cast<float4*>(&xs[(wb + er) * XST + (k4 << 2)]) =
                make_float4(a.x * b.x, a.y * b.y, a.z * b.z, a.w * b.w);
        }
        __syncwarp();

        float acc[2][8][4];
        ZERO_ACC(acc)
        mma_mainloop(xs, whi, wlo, wb, lane, acc);

#pragma unroll
        for (int mt = 0; mt < 2; mt++) {
            int dA = __shfl_sync(0xffffffffu, dval, mt * 16 + r);
            int dB = __shfl_sync(0xffffffffu, dval, mt * 16 + r + 8);
            float* pA = Cout + (size_t)dA * BASIS;
            float* pB = Cout + (size_t)dB * BASIS;
#pragma unroll
            for (int nt = 0; nt < 8; nt++) {
                float t0 = fast_tanh(acc[mt][nt][0]);
                float t1 = fast_tanh(acc[mt][nt][1]);
                float t2 = fast_tanh(acc[mt][nt][2]);
                float t3 = fast_tanh(acc[mt][nt][3]);
                float p0 = __shfl_xor_sync(0xffffffffu, t0, 1);
                float p1 = __shfl_xor_sync(0xffffffffu, t1, 1);
                float p2 = __shfl_xor_sync(0xffffffffu, t2, 1);
                float p3 = __shfl_xor_sync(0xffffffffu, t3, 1);
                if ((lane & 1) == 0) {
                    int col = nt * 8 + 2 * c;   // c even here
                    red_add_v4(pA + col, t0, t1, p0, p1);
                    red_add_v4(pB + col, t2, t3, p2, p3);
                }
            }
        }
        sval = sv_n;
        dval = dv_n;
    }
}

// Readout: out[batch[n]] += tanh(C@W1+b1)@W2 + b2, tensor-core, persistent.
__global__ void __launch_bounds__(256, 2) k_readout(const float* __restrict__ C,
                                                    const int* __restrict__ batch,
                                                    const float* __restrict__ b1,
                                                    const float* __restrict__ W2,
                                                    const float* __restrict__ b2,
                                                    float* __restrict__ out) {
    extern __shared__ float sm[];
    float* xs = sm;                                          // [256][68]
    uint2* whi = reinterpret_cast<uint2*>(sm + TILE * XST);  // [2048] (2 halves)
    uint2* wlo = whi + 2048;                                 // [2048]
    float4* W2s = reinterpret_cast<float4*>(wlo + 2048);     // [128]
    float* b1s = reinterpret_cast<float*>(W2s + 128);        // [128]

    int t = threadIdx.x;
    int lane = t & 31;
    int wb = (t >> 5) * 32;

    for (int i = t; i < 2048; i += 256) { whi[i] = g_W1hi[i]; wlo[i] = g_W1lo[i]; }
    if (t < HID) { W2s[t] = reinterpret_cast<const float4*>(W2)[t]; b1s[t] = b1[t]; }
    __syncthreads();

    float4 b2v = *reinterpret_cast<const float4*>(b2);
    int warpId = blockIdx.x * 8 + (t >> 5);
    const int NWP = GRID * 8;
    int tiles = (NN + 31) / 32;
    const float4* in4 = reinterpret_cast<const float4*>(C);
    int r = lane >> 2, c = lane & 3;

    for (int wt = warpId; wt < tiles; wt += NWP) {
        int n0 = wt * 32;
        int bval = (n0 + lane < NN) ? batch[n0 + lane] : 0;
        __syncwarp();
#pragma unroll
        for (int it = 0; it < 16; it++) {
            int j = it * 32 + lane;
            int e = j >> 4;
            int k4 = j & 15;
            float4 v = make_float4(0.f, 0.f, 0.f, 0.f);
            if (n0 + e < NN) v = in4[(size_t)(n0 + e) * 16 + k4];
            *reinterpret_cast<float4*>(&xs[(wb + e) * XST + (k4 << 2)]) = v;
        }
        __syncwarp();

        float o[4][4];
#pragma unroll
        for (int i = 0; i < 4; i++)
#pragma unroll
            for (int q = 0; q < 4; q++) o[i][q] = 0.0f;

#pragma unroll
        for (int hf = 0; hf < 2; hf++) {
            float acc[2][8][4];
            ZERO_ACC(acc)
            mma_mainloop(xs, whi + hf * 1024, wlo + hf * 1024, wb, lane, acc);
#pragma unroll
            for (int mt = 0; mt < 2; mt++)
#pragma unroll
                for (int nt = 0; nt < 8; nt++) {
                    int col = hf * 64 + nt * 8 + 2 * c;
                    float t0 = fast_tanh(acc[mt][nt][0] + b1s[col]);
                    float t1 = fast_tanh(acc[mt][nt][1] + b1s[col + 1]);
                    float t2 = fast_tanh(acc[mt][nt][2] + b1s[col]);
                    float t3 = fast_tanh(acc[mt][nt][3] + b1s[col + 1]);
                    float4 wa = W2s[col];
                    float4 wc = W2s[col + 1];
                    o[mt * 2 + 0][0] += t0 * wa.x + t1 * wc.x;
                    o[mt * 2 + 0][1] += t0 * wa.y + t1 * wc.y;
                    o[mt * 2 + 0][2] += t0 * wa.z + t1 * wc.z;
                    o[mt * 2 + 0][3] += t0 * wa.w + t1 * wc.w;
                    o[mt * 2 + 1][0] += t2 * wa.x + t3 * wc.x;
                    o[mt * 2 + 1][1] += t2 * wa.y + t3 * wc.y;
                    o[mt * 2 + 1][2] += t2 * wa.z + t3 * wc.z;
                    o[mt * 2 + 1][3] += t2 * wa.w + t3 * wc.w;
                }
        }
        // reduce over the 4 lanes sharing each row (c = 0..3)
#pragma unroll
        for (int i = 0; i < 4; i++)
#pragma unroll
            for (int q = 0; q < 4; q++) {
                o[i][q] += __shfl_xor_sync(0xffffffffu, o[i][q], 1);
                o[i][q] += __shfl_xor_sync(0xffffffffu, o[i][q], 2);
            }
#pragma unroll
        for (int mt = 0; mt < 2; mt++) {
            int row0 = mt * 16 + r;
            int row1 = row0 + 8;
            int g0 = __shfl_sync(0xffffffffu, bval, row0);
            int g1 = __shfl_sync(0xffffffffu, bval, row1);
            if (c == 0) {
                if (n0 + row0 < NN)
                    red_add_v4(out + (size_t)g0 * 4,
                               o[mt * 2][0] + b2v.x, o[mt * 2][1] + b2v.y,
                               o[mt * 2][2] + b2v.z, o[mt * 2][3] + b2v.w);
                if (n0 + row1 < NN)
                    red_add_v4(out + (size_t)g1 * 4,
                               o[mt * 2 + 1][0] + b2v.x, o[mt * 2 + 1][1] + b2v.y,
                               o[mt * 2 + 1][2] + b2v.z, o[mt * 2 + 1][3] + b2v.w);
            }
        }
    }
}

extern "C" void kernel_launch(void* const* d_in, const int* in_sizes, int n_in,
                              void* d_out, int out_size) {
    const int*   Z         = (const int*)d_in[0];
    const int*   ei        = (const int*)d_in[1];
    const float* edge_attr = (const float*)d_in[2];
    const int*   batch     = (const int*)d_in[3];
    const float* embed     = (const float*)d_in[4];
    const float* cfW       = (const float*)d_in[5];
    const float* cfb       = (const float*)d_in[6];
    const float* dfW       = (const float*)d_in[7];
    const float* dfb       = (const float*)d_in[8];
    const float* fcW       = (const float*)d_in[9];
    const float* W1        = (const float*)d_in[10];
    const float* b1        = (const float*)d_in[11];
    const float* W2        = (const float*)d_in[12];
    const float* b2        = (const float*)d_in[13];
    const int* src = ei;
    const int* dst = ei + NE;

    float *Ca, *nf, *dfeat;
    cudaGetSymbolAddress((void**)&Ca, g_Ca);
    cudaGetSymbolAddress((void**)&nf, g_nf);
    cudaGetSymbolAddress((void**)&dfeat, g_dfeat);

    const int SM_GEMM = TILE * XST * 4 + 2 * 1024 * 8 + 64 * 4;        // 86272
    const int SM_EDGE = TILE * XST * 4 + 2 * 1024 * 8;                 // 86016
    const int SM_RO   = TILE * XST * 4 + 2 * 2048 * 8 + 128 * 16 + 128 * 4;  // 105088
    cudaFuncSetAttribute(k_dfeat, cudaFuncAttributeMaxDynamicSharedMemorySize, SM_GEMM);
    cudaFuncSetAttribute(k_nodemv, cudaFuncAttributeMaxDynamicSharedMemorySize, SM_GEMM);
    cudaFuncSetAttribute(k_edge, cudaFuncAttributeMaxDynamicSharedMemorySize, SM_EDGE);
    cudaFuncSetAttribute(k_readout, cudaFuncAttributeMaxDynamicSharedMemorySize, SM_RO);

    k_prep<<<1, 256>>>(fcW, dfW, cfW, W1);
    k_init_C<<<(NN * BASIS + 255) / 256, 256>>>(Z, embed, Ca);
    k_dfeat<<<GRID, 256, SM_GEMM>>>(edge_attr, dfb, dfeat);

    for (int t = 0; t < 3; t++) {
        k_nodemv<<<GRID, 256, SM_GEMM>>>(Ca, cfb, nf);
        k_edge<<<GRID, 256, SM_EDGE>>>(nf, dfeat, src, dst, Ca);
    }

    k_zero<<<(NG * 4 + 255) / 256, 256>>>((float*)d_out, NG * 4);
    k_readout<<<GRID, 256, SM_RO>>>(Ca, batch, b1, W2, b2, (float*)d_out);
}

// round 9
// speedup vs baseline: 3.3678x; 1.0691x over previous
#include <cuda_runtime.h>
#include <cuda_fp16.h>
#include <cstdint>
#include <cstddef>

#define NN 50000
#define NE 800000
#define BASIS 64
#define HID 128
#define NG 512
#define SP 72            // smem stride in halves (144B rows; 16B-aligned ldmatrix rows)
#define WBLK_H 4608      // halves per warp block (hi 2304 + lo 2304) = 9216 bytes
#define GRID 296         // persistent: 2 blocks per SM

// Scratch (__device__ globals per allocation rules).
__device__ __align__(256) float g_dfeat[(size_t)NE * BASIS];
__device__ __align__(256) float g_nf[(size_t)NN * BASIS];
__device__ __align__(256) float g_Ca[(size_t)NN * BASIS];
// Combined fp16 hi/lo B-fragment tables: [kc 4][nt 8][lane 32] -> uint4 {bh.x,bh.y,bl.x,bl.y}
__device__ __align__(256) uint4 g_fcW[1024];
__device__ __align__(256) uint4 g_dfW[1024];
__device__ __align__(256) uint4 g_cfW[1024];
__device__ __align__(256) uint4 g_W1[2048];   // two 64-col halves

__device__ __forceinline__ float fast_tanh(float v) {
    float y;
    asm("tanh.approx.f32 %0, %1;" : "=f"(y) : "f"(v));
    return y;
}
__device__ __forceinline__ void red_add_v4(float* p, float a, float b, float c, float d) {
    asm volatile("red.global.add.v4.f32 [%0], {%1, %2, %3, %4};"
                 :: "l"(p), "f"(a), "f"(b), "f"(c), "f"(d) : "memory");
}
__device__ __forceinline__ unsigned pack_h2(float x, float y) {
    __half2 h = __floats2half2_rn(x, y);
    return *reinterpret_cast<unsigned*>(&h);
}
__device__ __forceinline__ unsigned split_hi(float2 v, float2& rest) {
    __half2 h = __floats2half2_rn(v.x, v.y);
    rest.x = v.x - __low2float(h);
    rest.y = v.y - __high2float(h);
    return *reinterpret_cast<unsigned*>(&h);
}
__device__ __forceinline__ void split4(float4 v, uint2& hi, uint2& lo) {
    float2 r01, r23;
    unsigned h01 = split_hi(make_float2(v.x, v.y), r01);
    unsigned h23 = split_hi(make_float2(v.z, v.w), r23);
    hi = make_uint2(h01, h23);
    lo = make_uint2(pack_h2(r01.x, r01.y), pack_h2(r23.x, r23.y));
}
__device__ __forceinline__ void mma_fp16(float* d, const unsigned* a, unsigned bx, unsigned by) {
    asm volatile(
        "mma.sync.aligned.m16n8k16.row.col.f32.f16.f16.f32 "
        "{%0,%1,%2,%3}, {%4,%5,%6,%7}, {%8,%9}, {%0,%1,%2,%3};"
        : "+f"(d[0]), "+f"(d[1]), "+f"(d[2]), "+f"(d[3])
        : "r"(a[0]), "r"(a[1]), "r"(a[2]), "r"(a[3]), "r"(bx), "r"(by));
}
__device__ __forceinline__ void ldm_x4(uint32_t addr, unsigned r[4]) {
    asm volatile("ldmatrix.sync.aligned.m8n8.x4.shared.b16 {%0,%1,%2,%3}, [%4];"
                 : "=r"(r[0]), "=r"(r[1]), "=r"(r[2]), "=r"(r[3]) : "r"(addr));
}

// Build combined permuted fp16 hi/lo fragment tables (out = x @ W).
__global__ void __launch_bounds__(256) k_prep(const float* __restrict__ fcW,
                                              const float* __restrict__ dfW,
                                              const float* __restrict__ cfW,
                                              const float* __restrict__ W1) {
    for (int idx = threadIdx.x; idx < 1024; idx += 256) {
        int kc = idx >> 8;
        int nt = (idx >> 5) & 7;
        int lane = idx & 31;
        int n = nt * 8 + (lane >> 2);
        int k0 = kc * 16 + (lane & 3) * 2;
        const float* Ws[3] = {fcW, dfW, cfW};
        uint4* T[3] = {g_fcW, g_dfW, g_cfW};
#pragma unroll
        for (int w = 0; w < 3; w++) {
            float w00 = Ws[w][(k0 + 0) * BASIS + n];
            float w01 = Ws[w][(k0 + 1) * BASIS + n];
            float w10 = Ws[w][(k0 + 8) * BASIS + n];
            float w11 = Ws[w][(k0 + 9) * BASIS + n];
            float2 r0, r1;
            uint4 e;
            e.x = split_hi(make_float2(w00, w01), r0);
            e.y = split_hi(make_float2(w10, w11), r1);
            e.z = pack_h2(r0.x, r0.y);
            e.w = pack_h2(r1.x, r1.y);
            T[w][idx] = e;
        }
    }
    for (int idx = threadIdx.x; idx < 2048; idx += 256) {
        int hf = idx >> 10;
        int rest = idx & 1023;
        int kc = rest >> 8;
        int nt = (rest >> 5) & 7;
        int lane = rest & 31;
        int n = hf * 64 + nt * 8 + (lane >> 2);
        int k0 = kc * 16 + (lane & 3) * 2;
        float w00 = W1[(k0 + 0) * HID + n];
        float w01 = W1[(k0 + 1) * HID + n];
        float w10 = W1[(k0 + 8) * HID + n];
        float w11 = W1[(k0 + 9) * HID + n];
        float2 r0, r1;
        uint4 e;
        e.x = split_hi(make_float2(w00, w01), r0);
        e.y = split_hi(make_float2(w10, w11), r1);
        e.z = pack_h2(r0.x, r0.y);
        e.w = pack_h2(r1.x, r1.y);
        g_W1[idx] = e;
    }
}

__global__ void __launch_bounds__(256) k_init_C(const int* __restrict__ Z,
                                                const float* __restrict__ embed,
                                                float* __restrict__ C) {
    int idx = blockIdx.x * blockDim.x + threadIdx.x;
    if (idx >= NN * BASIS) return;
    C[idx] = embed[Z[idx >> 6] * BASIS + (idx & 63)];
}

__global__ void __launch_bounds__(256) k_zero(float* __restrict__ p, int n) {
    int i = blockIdx.x * blockDim.x + threadIdx.x;
    if (i < n) p[i] = 0.0f;
}

// ---------------------------------------------------------------------------
// ldmatrix mainloop: acc += tile @ W (3-product fp16 Markidis). A-fragments
// from pre-split per-warp smem planes (hi at block+0, lo at block+2304h).
// ---------------------------------------------------------------------------
__device__ __forceinline__ void mma_mainloop(uint32_t aHi,
                                             const uint4* __restrict__ whl,
                                             int lane, float acc[2][8][4]) {
    uint32_t aLo = aHi + (unsigned)(2304 * 2);
#pragma unroll
    for (int kc = 0; kc < 4; kc++) {
        unsigned ah[2][4], al[2][4];
#pragma unroll
        for (int mt = 0; mt < 2; mt++) {
            uint32_t off = (unsigned)(mt * 16 * SP + kc * 16) * 2u;
            ldm_x4(aHi + off, ah[mt]);
            ldm_x4(aLo + off, al[mt]);
        }
#pragma unroll
        for (int nt = 0; nt < 8; nt++) {
            uint4 w = whl[(kc * 8 + nt) * 32 + lane];
#pragma unroll
            for (int mt = 0; mt < 2; mt++) {
                mma_fp16(acc[mt][nt], ah[mt], w.x, w.y);
                mma_fp16(acc[mt][nt], al[mt], w.x, w.y);
                mma_fp16(acc[mt][nt], ah[mt], w.z, w.w);
            }
        }
    }
}

#define ZERO_ACC(acc)                                   \
    _Pragma("unroll")                                   \
    for (int mt = 0; mt < 2; mt++)                      \
        _Pragma("unroll")                               \
        for (int nt = 0; nt < 8; nt++)                  \
            _Pragma("unroll")                           \
            for (int q = 0; q < 4; q++) acc[mt][nt][q] = 0.0f;

// per-lane ldmatrix role: row / k-offset within the warp tile
#define LDM_ROLE(lane, rowoff, koff)                 \
    int rowoff = ((lane >> 3) & 1) * 8 + (lane & 7); \
    int koff = ((lane >> 4) & 1) * 8;

// Persistent tiled row-GEMM: out = in @ W + bias. Per-warp 9216B smem block.
__device__ __forceinline__ void rowgemm_body(const float* __restrict__ in,
                                             const uint4* __restrict__ gW,
                                             const float* __restrict__ bias,
                                             float* __restrict__ out,
                                             int nrows) {
    extern __shared__ char smc[];
    __half* xsh = reinterpret_cast<__half*>(smc);                 // 8 warp blocks
    uint4* whl = reinterpret_cast<uint4*>(smc + 73728);           // [1024]
    float* bs = reinterpret_cast<float*>(smc + 73728 + 16384);    // [64]

    int t = threadIdx.x;
    int lane = t & 31;
    int w = t >> 5;
    int wblk = w * WBLK_H;                                        // half offset
    float* fs = reinterpret_cast<float*>(smc + w * (WBLK_H * 2)); // warp-own 32x68 floats

    for (int i = t; i < 1024; i += 256) whl[i] = gW[i];
    if (t < BASIS) bs[t] = bias[t];
    __syncthreads();   // tables ready; everything below is warp-local

    LDM_ROLE(lane, rowoff, koff)
    uint32_t aHi = (uint32_t)__cvta_generic_to_shared(xsh) +
                   (unsigned)(wblk + rowoff * SP + koff) * 2u;

    int warpId = blockIdx.x * 8 + w;
    const int NWP = GRID * 8;
    int tiles = (nrows + 31) / 32;
    const float4* in4 = reinterpret_cast<const float4*>(in);
    float4* o4 = reinterpret_cast<float4*>(out);
    int r = lane >> 2, c = lane & 3;

    for (int wt = warpId; wt < tiles; wt += NWP) {
        int n0 = wt * 32;
        __syncwarp();
#pragma unroll
        for (int it = 0; it < 16; it++) {
            int j = it * 32 + lane;
            int e = j >> 4;
            int k4 = j & 15;
            float4 v = make_float4(0.f, 0.f, 0.f, 0.f);
            if (n0 + e < nrows) v = in4[(size_t)(n0 + e) * 16 + k4];
            uint2 hi, lo;
            split4(v, hi, lo);
            *reinterpret_cast<uint2*>(&xsh[wblk + e * SP + k4 * 4]) = hi;
            *reinterpret_cast<uint2*>(&xsh[wblk + 2304 + e * SP + k4 * 4]) = lo;
        }
        __syncwarp();

        float acc[2][8][4];
        ZERO_ACC(acc)
        mma_mainloop(aHi, whl, lane, acc);
        __syncwarp();   // switch warp block to float scratch

#pragma unroll
        for (int mt = 0; mt < 2; mt++)
#pragma unroll
            for (int nt = 0; nt < 8; nt++) {
                int col = nt * 8 + 2 * c;
                int e = mt * 16 + r;       // local row 0..31
                float b0 = bs[col], b1 = bs[col + 1];
                *reinterpret_cast<float2*>(&fs[e * 68 + col]) =
                    make_float2(acc[mt][nt][0] + b0, acc[mt][nt][1] + b1);
                *reinterpret_cast<float2*>(&fs[(e + 8) * 68 + col]) =
                    make_float2(acc[mt][nt][2] + b0, acc[mt][nt][3] + b1);
            }
        __syncwarp();

#pragma unroll
        for (int it = 0; it < 16; it++) {
            int j = it * 32 + lane;
            int e = j >> 4;
            int k4 = j & 15;
            if (n0 + e < nrows)
                o4[(size_t)(n0 + e) * 16 + k4] =
                    *reinterpret_cast<const float4*>(&fs[e * 68 + (k4 << 2)]);
        }
    }
}

__global__ void __launch_bounds__(256, 2) k_dfeat(const float* __restrict__ in,
                                                  const float* __restrict__ bias,
                                                  float* __restrict__ out) {
    rowgemm_body(in, g_dfW, bias, out, NE);
}

__global__ void __launch_bounds__(256, 2) k_nodemv(const float* __restrict__ C,
                                                   const float* __restrict__ bias,
                                                   float* __restrict__ out) {
    rowgemm_body(C, g_cfW, bias, out, NN);
}

// Edge kernel: C[dst] += tanh( (nf[src] * dfeat) @ fcW )
__global__ void __launch_bounds__(256, 2) k_edge(const float* __restrict__ nf,
                                                 const float* __restrict__ dfeat,
                                                 const int* __restrict__ src,
                                                 const int* __restrict__ dst,
                                                 float* __restrict__ Cout) {
    extern __shared__ char smc[];
    __half* xsh = reinterpret_cast<__half*>(smc);
    uint4* whl = reinterpret_cast<uint4*>(smc + 73728);   // [1024]

    int t = threadIdx.x;
    int lane = t & 31;
    int w = t >> 5;
    int wblk = w * WBLK_H;

    for (int i = t; i < 1024; i += 256) whl[i] = g_fcW[i];
    __syncthreads();

    LDM_ROLE(lane, rowoff, koff)
    uint32_t aHi = (uint32_t)__cvta_generic_to_shared(xsh) +
                   (unsigned)(wblk + rowoff * SP + koff) * 2u;

    int warpId = blockIdx.x * 8 + w;
    const int NWP = GRID * 8;
    const int tiles = NE / 32;
    const float4* nf4 = reinterpret_cast<const float4*>(nf);
    const float4* df4 = reinterpret_cast<const float4*>(dfeat);
    int r = lane >> 2, c = lane & 3;

    int wt = warpId;
    int sval = 0, dval = 0;
    if (wt < tiles) {
        sval = src[(size_t)wt * 32 + lane];
        dval = dst[(size_t)wt * 32 + lane];
    }
    for (; wt < tiles; wt += NWP) {
        int wn = wt + NWP;
        int sv_n = 0, dv_n = 0;
        if (wn < tiles) {
            sv_n = src[(size_t)wn * 32 + lane];
            dv_n = dst[(size_t)wn * 32 + lane];
        }
        __syncwarp();
#pragma unroll
        for (int it = 0; it < 16; it++) {
            int j = it * 32 + lane;
            int er = j >> 4;
            int k4 = j & 15;
            int s = __shfl_sync(0xffffffffu, sval, er);
            float4 a = nf4[(size_t)s * 16 + k4];
            float4 b = df4[((size_t)wt * 32 + er) * 16 + k4];
            float4 v = make_float4(a.x * b.x, a.y * b.y, a.z * b.z, a.w * b.w);
            uint2 hi, lo;
            split4(v, hi, lo);
            *reinterpret_cast<uint2*>(&xsh[wblk + er * SP + k4 * 4]) = hi;
            *reinterpret_cast<uint2*>(&xsh[wblk + 2304 + er * SP + k4 * 4]) = lo;
        }
        __syncwarp();

        float acc[2][8][4];
        ZERO_ACC(acc)
        mma_mainloop(aHi, whl, lane, acc);

#pragma unroll
        for (int mt = 0; mt < 2; mt++) {
            int dA = __shfl_sync(0xffffffffu, dval, mt * 16 + r);
            int dB = __shfl_sync(0xffffffffu, dval, mt * 16 + r + 8);
            float* pA = Cout + (size_t)dA * BASIS;
            float* pB = Cout + (size_t)dB * BASIS;
#pragma unroll
            for (int nt = 0; nt < 8; nt++) {
                float t0 = fast_tanh(acc[mt][nt][0]);
                float t1 = fast_tanh(acc[mt][nt][1]);
                float t2 = fast_tanh(acc[mt][nt][2]);
                float t3 = fast_tanh(acc[mt][nt][3]);
                float p0 = __shfl_xor_sync(0xffffffffu, t0, 1);
                float p1 = __shfl_xor_sync(0xffffffffu, t1, 1);
                float p2 = __shfl_xor_sync(0xffffffffu, t2, 1);
                float p3 = __shfl_xor_sync(0xffffffffu, t3, 1);
                if ((lane & 1) == 0) {
                    int col = nt * 8 + 2 * c;
                    red_add_v4(pA + col, t0, t1, p0, p1);
                    red_add_v4(pB + col, t2, t3, p2, p3);
                }
            }
        }
        sval = sv_n;
        dval = dv_n;
    }
}

// Readout: out[batch[n]] += tanh(C@W1+b1)@W2 + b2
__global__ void __launch_bounds__(256, 2) k_readout(const float* __restrict__ C,
                                                    const int* __restrict__ batch,
                                                    const float* __restrict__ b1,
                                                    const float* __restrict__ W2,
                                                    const float* __restrict__ b2,
                                                    float* __restrict__ out) {
    extern __shared__ char smc[];
    __half* xsh = reinterpret_cast<__half*>(smc);
    uint4* whl = reinterpret_cast<uint4*>(smc + 73728);            // [2048]
    float4* W2s = reinterpret_cast<float4*>(smc + 73728 + 32768);  // [128]
    float* b1s = reinterpret_cast<float*>(smc + 73728 + 32768 + 2048);  // [128]

    int t = threadIdx.x;
    int lane = t & 31;
    int w = t >> 5;
    int wblk = w * WBLK_H;

    for (int i = t; i < 2048; i += 256) whl[i] = g_W1[i];
    if (t < HID) { W2s[t] = reinterpret_cast<const float4*>(W2)[t]; b1s[t] = b1[t]; }
    __syncthreads();

    LDM_ROLE(lane, rowoff, koff)
    uint32_t aHi = (uint32_t)__cvta_generic_to_shared(xsh) +
                   (unsigned)(wblk + rowoff * SP + koff) * 2u;

    float4 b2v = *reinterpret_cast<const float4*>(b2);
    int warpId = blockIdx.x * 8 + w;
    const int NWP = GRID * 8;
    int tiles = (NN + 31) / 32;
    const float4* in4 = reinterpret_cast<const float4*>(C);
    int r = lane >> 2, c = lane & 3;

    for (int wt = warpId; wt < tiles; wt += NWP) {
        int n0 = wt * 32;
        int bval = (n0 + lane < NN) ? batch[n0 + lane] : 0;
        __syncwarp();
#pragma unroll
        for (int it = 0; it < 16; it++) {
            int j = it * 32 + lane;
            int e = j >> 4;
            int k4 = j & 15;
            float4 v = make_float4(0.f, 0.f, 0.f, 0.f);
            if (n0 + e < NN) v = in4[(size_t)(n0 + e) * 16 + k4];
            uint2 hi, lo;
            split4(v, hi, lo);
            *reinterpret_cast<uint2*>(&xsh[wblk + e * SP + k4 * 4]) = hi;
            *reinterpret_cast<uint2*>(&xsh[wblk + 2304 + e * SP + k4 * 4]) = lo;
        }
        __syncwarp();

        float o[4][4];
#pragma unroll
        for (int i = 0; i < 4; i++)
#pragma unroll
            for (int q = 0; q < 4; q++) o[i][q] = 0.0f;

#pragma unroll
        for (int hf = 0; hf < 2; hf++) {
            float acc[2][8][4];
            ZERO_ACC(acc)
            mma_mainloop(aHi, whl + hf * 1024, lane, acc);
#pragma unroll
            for (int mt = 0; mt < 2; mt++)
#pragma unroll
                for (int nt = 0; nt < 8; nt++) {
                    int col = hf * 64 + nt * 8 + 2 * c;
                    float t0 = fast_tanh(acc[mt][nt][0] + b1s[col]);
                    float t1 = fast_tanh(acc[mt][nt][1] + b1s[col + 1]);
                    float t2 = fast_tanh(acc[mt][nt][2] + b1s[col]);
                    float t3 = fast_tanh(acc[mt][nt][3] + b1s[col + 1]);
                    float4 wa = W2s[col];
                    float4 wc = W2s[col + 1];
                    o[mt * 2 + 0][0] += t0 * wa.x + t1 * wc.x;
                    o[mt * 2 + 0][1] += t0 * wa.y + t1 * wc.y;
                    o[mt * 2 + 0][2] += t0 * wa.z + t1 * wc.z;
                    o[mt * 2 + 0][3] += t0 * wa.w + t1 * wc.w;
                    o[mt * 2 + 1][0] += t2 * wa.x + t3 * wc.x;
                    o[mt * 2 + 1][1] += t2 * wa.y + t3 * wc.y;
                    o[mt * 2 + 1][2] += t2 * wa.z + t3 * wc.z;
                    o[mt * 2 + 1][3] += t2 * wa.w + t3 * wc.w;
                }
        }
#pragma unroll
        for (int i = 0; i < 4; i++)
#pragma unroll
            for (int q = 0; q < 4; q++) {
                o[i][q] += __shfl_xor_sync(0xffffffffu, o[i][q], 1);
                o[i][q] += __shfl_xor_sync(0xffffffffu, o[i][q], 2);
            }
#pragma unroll
        for (int mt = 0; mt < 2; mt++) {
            int row0 = mt * 16 + r;
            int row1 = row0 + 8;
            int g0 = __shfl_sync(0xffffffffu, bval, row0);
            int g1 = __shfl_sync(0xffffffffu, bval, row1);
            if (c == 0) {
                if (n0 + row0 < NN)
                    red_add_v4(out + (size_t)g0 * 4,
                               o[mt * 2][0] + b2v.x, o[mt * 2][1] + b2v.y,
                               o[mt * 2][2] + b2v.z, o[mt * 2][3] + b2v.w);
                if (n0 + row1 < NN)
                    red_add_v4(out + (size_t)g1 * 4,
                               o[mt * 2 + 1][0] + b2v.x, o[mt * 2 + 1][1] + b2v.y,
                               o[mt * 2 + 1][2] + b2v.z, o[mt * 2 + 1][3] + b2v.w);
            }
        }
    }
}

extern "C" void kernel_launch(void* const* d_in, const int* in_sizes, int n_in,
                              void* d_out, int out_size) {
    const int*   Z         = (const int*)d_in[0];
    const int*   ei        = (const int*)d_in[1];
    const float* edge_attr = (const float*)d_in[2];
    const int*   batch     = (const int*)d_in[3];
    const float* embed     = (const float*)d_in[4];
    const float* cfW       = (const float*)d_in[5];
    const float* cfb       = (const float*)d_in[6];
    const float* dfW       = (const float*)d_in[7];
    const float* dfb       = (const float*)d_in[8];
    const float* fcW       = (const float*)d_in[9];
    const float* W1        = (const float*)d_in[10];
    const float* b1        = (const float*)d_in[11];
    const float* W2        = (const float*)d_in[12];
    const float* b2        = (const float*)d_in[13];
    const int* src = ei;
    const int* dst = ei + NE;

    float *Ca, *nf, *dfeat;
    cudaGetSymbolAddress((void**)&Ca, g_Ca);
    cudaGetSymbolAddress((void**)&nf, g_nf);
    cudaGetSymbolAddress((void**)&dfeat, g_dfeat);

    const int SM_GEMM = 73728 + 16384 + 256;            // 90368
    const int SM_EDGE = 73728 + 16384;                   // 90112
    const int SM_RO   = 73728 + 32768 + 2048 + 512;      // 109056
    cudaFuncSetAttribute(k_dfeat, cudaFuncAttributeMaxDynamicSharedMemorySize, SM_GEMM);
    cudaFuncSetAttribute(k_nodemv, cudaFuncAttributeMaxDynamicSharedMemorySize, SM_GEMM);
    cudaFuncSetAttribute(k_edge, cudaFuncAttributeMaxDynamicSharedMemorySize, SM_EDGE);
    cudaFuncSetAttribute(k_readout, cudaFuncAttributeMaxDynamicSharedMemorySize, SM_RO);

    k_prep<<<1, 256>>>(fcW, dfW, cfW, W1);
    k_init_C<<<(NN * BASIS + 255) / 256, 256>>>(Z, embed, Ca);
    k_dfeat<<<GRID, 256, SM_GEMM>>>(edge_attr, dfb, dfeat);

    for (int t = 0; t < 3; t++) {
        k_nodemv<<<GRID, 256, SM_GEMM>>>(Ca, cfb, nf);
        k_edge<<<GRID, 256, SM_EDGE>>>(nf, dfeat, src, dst, Ca);
    }

    k_zero<<<(NG * 4 + 255) / 256, 256>>>((float*)d_out, NG * 4);
    k_readout<<<GRID, 256, SM_RO>>>(Ca, batch, b1, W2, b2, (float*)d_out);
}

// round 11
// speedup vs baseline: 3.4089x; 1.0122x over previous
#include <cuda_runtime.h>
#include <cuda_fp16.h>
#include <cstdint>
#include <cstddef>

#define NN 50000
#define NE 800000
#define BASIS 64
#define HID 128
#define NG 512
#define SP 72            // smem stride in halves (144B rows)
#define WBLK_H 2304      // halves per warp block (hi 1152 + lo 1152) = 4608 bytes
#define GRID 444         // persistent: 3 blocks per SM

// Scratch (__device__ globals per allocation rules).
__device__ __align__(256) float g_dfeat[(size_t)NE * BASIS];
__device__ __align__(256) float g_nf[(size_t)NN * BASIS];
__device__ __align__(256) float g_Ca[(size_t)NN * BASIS];
// Combined fp16 hi/lo B-fragment tables: [kc 4][nt 8][lane 32] -> uint4 {bh.x,bh.y,bl.x,bl.y}
__device__ __align__(256) uint4 g_fcW[1024];
__device__ __align__(256) uint4 g_dfW[1024];
__device__ __align__(256) uint4 g_cfW[1024];
__device__ __align__(256) uint4 g_W1[2048];   // two 64-col halves

__device__ __forceinline__ float fast_tanh(float v) {
    float y;
    asm("tanh.approx.f32 %0, %1;" : "=f"(y) : "f"(v));
    return y;
}
__device__ __forceinline__ void red_add_v4(float* p, float a, float b, float c, float d) {
    asm volatile("red.global.add.v4.f32 [%0], {%1, %2, %3, %4};"
                 :: "l"(p), "f"(a), "f"(b), "f"(c), "f"(d) : "memory");
}
__device__ __forceinline__ unsigned pack_h2(float x, float y) {
    __half2 h = __floats2half2_rn(x, y);
    return *reinterpret_cast<unsigned*>(&h);
}
__device__ __forceinline__ unsigned split_hi(float2 v, float2& rest) {
    __half2 h = __floats2half2_rn(v.x, v.y);
    rest.x = v.x - __low2float(h);
    rest.y = v.y - __high2float(h);
    return *reinterpret_cast<unsigned*>(&h);
}
__device__ __forceinline__ void split4(float4 v, uint2& hi, uint2& lo) {
    float2 r01, r23;
    unsigned h01 = split_hi(make_float2(v.x, v.y), r01);
    unsigned h23 = split_hi(make_float2(v.z, v.w), r23);
    hi = make_uint2(h01, h23);
    lo = make_uint2(pack_h2(r01.x, r01.y), pack_h2(r23.x, r23.y));
}
__device__ __forceinline__ void mma_fp16(float* d, const unsigned* a, unsigned bx, unsigned by) {
    asm volatile(
        "mma.sync.aligned.m16n8k16.row.col.f32.f16.f16.f32 "
        "{%0,%1,%2,%3}, {%4,%5,%6,%7}, {%8,%9}, {%0,%1,%2,%3};"
        : "+f"(d[0]), "+f"(d[1]), "+f"(d[2]), "+f"(d[3])
        : "r"(a[0]), "r"(a[1]), "r"(a[2]), "r"(a[3]), "r"(bx), "r"(by));
}
__device__ __forceinline__ void ldm_x4(uint32_t addr, unsigned r[4]) {
    asm volatile("ldmatrix.sync.aligned.m8n8.x4.shared.b16 {%0,%1,%2,%3}, [%4];"
                 : "=r"(r[0]), "=r"(r[1]), "=r"(r[2]), "=r"(r[3]) : "r"(addr));
}

// Build combined permuted fp16 hi/lo fragment tables (out = x @ W).
__global__ void __launch_bounds__(256) k_prep(const float* __restrict__ fcW,
                                              const float* __restrict__ dfW,
                                              const float* __restrict__ cfW,
                                              const float* __restrict__ W1) {
    for (int idx = threadIdx.x; idx < 1024; idx += 256) {
        int kc = idx >> 8;
        int nt = (idx >> 5) & 7;
        int lane = idx & 31;
        int n = nt * 8 + (lane >> 2);
        int k0 = kc * 16 + (lane & 3) * 2;
        const float* Ws[3] = {fcW, dfW, cfW};
        uint4* T[3] = {g_fcW, g_dfW, g_cfW};
#pragma unroll
        for (int w = 0; w < 3; w++) {
            float w00 = Ws[w][(k0 + 0) * BASIS + n];
            float w01 = Ws[w][(k0 + 1) * BASIS + n];
            float w10 = Ws[w][(k0 + 8) * BASIS + n];
            float w11 = Ws[w][(k0 + 9) * BASIS + n];
            float2 r0, r1;
            uint4 e;
            e.x = split_hi(make_float2(w00, w01), r0);
            e.y = split_hi(make_float2(w10, w11), r1);
            e.z = pack_h2(r0.x, r0.y);
            e.w = pack_h2(r1.x, r1.y);
            T[w][idx] = e;
        }
    }
    for (int idx = threadIdx.x; idx < 2048; idx += 256) {
        int hf = idx >> 10;
        int rest = idx & 1023;
        int kc = rest >> 8;
        int nt = (rest >> 5) & 7;
        int lane = rest & 31;
        int n = hf * 64 + nt * 8 + (lane >> 2);
        int k0 = kc * 16 + (lane & 3) * 2;
        float w00 = W1[(k0 + 0) * HID + n];
        float w01 = W1[(k0 + 1) * HID + n];
        float w10 = W1[(k0 + 8) * HID + n];
        float w11 = W1[(k0 + 9) * HID + n];
        float2 r0, r1;
        uint4 e;
        e.x = split_hi(make_float2(w00, w01), r0);
        e.y = split_hi(make_float2(w10, w11), r1);
        e.z = pack_h2(r0.x, r0.y);
        e.w = pack_h2(r1.x, r1.y);
        g_W1[idx] = e;
    }
}

__global__ void __launch_bounds__(256) k_init_C(const int* __restrict__ Z,
                                                const float* __restrict__ embed,
                                                float* __restrict__ C) {
    int idx = blockIdx.x * blockDim.x + threadIdx.x;
    if (idx >= NN * BASIS) return;
    C[idx] = embed[Z[idx >> 6] * BASIS + (idx & 63)];
}

__global__ void __launch_bounds__(256) k_zero(float* __restrict__ p, int n) {
    int i = blockIdx.x * blockDim.x + threadIdx.x;
    if (i < n) p[i] = 0.0f;
}

// ---------------------------------------------------------------------------
// ldmatrix mainloop, 16-row warp tile: acc[8][4] += tile @ W (3-product fp16).
// ---------------------------------------------------------------------------
__device__ __forceinline__ void mma_mainloop(uint32_t aHi,
                                             const uint4* __restrict__ whl,
                                             int lane, float acc[8][4]) {
    uint32_t aLo = aHi + (unsigned)(1152 * 2);
#pragma unroll
    for (int kc = 0; kc < 4; kc++) {
        unsigned ah[4], al[4];
        uint32_t off = (unsigned)(kc * 16) * 2u;
        ldm_x4(aHi + off, ah);
        ldm_x4(aLo + off, al);
#pragma unroll
        for (int nt = 0; nt < 8; nt++) {
            uint4 wv = whl[(kc * 8 + nt) * 32 + lane];
            mma_fp16(acc[nt], ah, wv.x, wv.y);
            mma_fp16(acc[nt], al, wv.x, wv.y);
            mma_fp16(acc[nt], ah, wv.z, wv.w);
        }
    }
}

#define ZERO_ACC(acc)                               \
    _Pragma("unroll")                               \
    for (int nt = 0; nt < 8; nt++)                  \
        _Pragma("unroll")                           \
        for (int q = 0; q < 4; q++) acc[nt][q] = 0.0f;

// per-lane ldmatrix role: row / k-offset within the 16-row warp tile
#define LDM_ROLE(lane, rowoff, koff)                 \
    int rowoff = ((lane >> 3) & 1) * 8 + (lane & 7); \
    int koff = ((lane >> 4) & 1) * 8;

// Persistent tiled row-GEMM: out = in @ W + bias. 16-row warp tiles.
__device__ __forceinline__ void rowgemm_body(const float* __restrict__ in,
                                             const uint4* __restrict__ gW,
                                             const float* __restrict__ bias,
                                             float* __restrict__ out,
                                             int nrows) {
    extern __shared__ char smc[];
    __half* xsh = reinterpret_cast<__half*>(smc);                 // 8 warp blocks x 4608B
    uint4* whl = reinterpret_cast<uint4*>(smc + 36864);           // [1024]
    float* bs = reinterpret_cast<float*>(smc + 36864 + 16384);    // [64]

    int t = threadIdx.x;
    int lane = t & 31;
    int w = t >> 5;
    int wblk = w * WBLK_H;                                        // half offset
    float* fs = reinterpret_cast<float*>(smc + w * (WBLK_H * 2)); // warp-own 16x68 floats

    for (int i = t; i < 1024; i += 256) whl[i] = gW[i];
    if (t < BASIS) bs[t] = bias[t];
    __syncthreads();   // tables ready; everything below is warp-local

    LDM_ROLE(lane, rowoff, koff)
    uint32_t aHi = (uint32_t)__cvta_generic_to_shared(xsh) +
                   (unsigned)(wblk + rowoff * SP + koff) * 2u;

    int warpId = blockIdx.x * 8 + w;
    const int NWP = GRID * 8;
    int tiles = (nrows + 15) / 16;
    const float4* in4 = reinterpret_cast<const float4*>(in);
    float4* o4 = reinterpret_cast<float4*>(out);
    int r = lane >> 2, c = lane & 3;

    for (int wt = warpId; wt < tiles; wt += NWP) {
        int n0 = wt * 16;
        __syncwarp();
#pragma unroll
        for (int it = 0; it < 8; it++) {
            int j = it * 32 + lane;
            int e = j >> 4;
            int k4 = j & 15;
            float4 v = make_float4(0.f, 0.f, 0.f, 0.f);
            if (n0 + e < nrows) v = in4[(size_t)(n0 + e) * 16 + k4];
            uint2 hi, lo;
            split4(v, hi, lo);
            *reinterpret_cast<uint2*>(&xsh[wblk + e * SP + k4 * 4]) = hi;
            *reinterpret_cast<uint2*>(&xsh[wblk + 1152 + e * SP + k4 * 4]) = lo;
        }
        __syncwarp();

        float acc[8][4];
        ZERO_ACC(acc)
        mma_mainloop(aHi, whl, lane, acc);
        __syncwarp();   // switch warp block to float scratch

#pragma unroll
        for (int nt = 0; nt < 8; nt++) {
            int col = nt * 8 + 2 * c;
            float b0 = bs[col], b1 = bs[col + 1];
            *reinterpret_cast<float2*>(&fs[r * 68 + col]) =
                make_float2(acc[nt][0] + b0, acc[nt][1] + b1);
            *reinterpret_cast<float2*>(&fs[(r + 8) * 68 + col]) =
                make_float2(acc[nt][2] + b0, acc[nt][3] + b1);
        }
        __syncwarp();

#pragma unroll
        for (int it = 0; it < 8; it++) {
            int j = it * 32 + lane;
            int e = j >> 4;
            int k4 = j & 15;
            if (n0 + e < nrows)
                o4[(size_t)(n0 + e) * 16 + k4] =
                    *reinterpret_cast<const float4*>(&fs[e * 68 + (k4 << 2)]);
        }
    }
}

__global__ void __launch_bounds__(256, 3) k_dfeat(const float* __restrict__ in,
                                                  const float* __restrict__ bias,
                                                  float* __restrict__ out) {
    rowgemm_body(in, g_dfW, bias, out, NE);
}

__global__ void __launch_bounds__(256, 3) k_nodemv(const float* __restrict__ C,
                                                   const float* __restrict__ bias,
                                                   float* __restrict__ out) {
    rowgemm_body(C, g_cfW, bias, out, NN);
}

// Edge kernel: C[dst] += tanh( (nf[src] * dfeat) @ fcW )
__global__ void __launch_bounds__(256, 3) k_edge(const float* __restrict__ nf,
                                                 const float* __restrict__ dfeat,
                                                 const int* __restrict__ src,
                                                 const int* __restrict__ dst,
                                                 float* __restrict__ Cout) {
    extern __shared__ char smc[];
    __half* xsh = reinterpret_cast<__half*>(smc);
    uint4* whl = reinterpret_cast<uint4*>(smc + 36864);   // [1024]

    int t = threadIdx.x;
    int lane = t & 31;
    int w = t >> 5;
    int wblk = w * WBLK_H;

    for (int i = t; i < 1024; i += 256) whl[i] = g_fcW[i];
    __syncthreads();

    LDM_ROLE(lane, rowoff, koff)
    uint32_t aHi = (uint32_t)__cvta_generic_to_shared(xsh) +
                   (unsigned)(wblk + rowoff * SP + koff) * 2u;

    int warpId = blockIdx.x * 8 + w;
    const int NWP = GRID * 8;
    const int tiles = NE / 16;   // 50000 exact
    const float4* nf4 = reinterpret_cast<const float4*>(nf);
    const float4* df4 = reinterpret_cast<const float4*>(dfeat);
    int r = lane >> 2, c = lane & 3;

    int wt = warpId;
    int sval = 0, dval = 0;
    if (wt < tiles) {
        sval = src[(size_t)wt * 16 + (lane & 15)];
        dval = dst[(size_t)wt * 16 + (lane & 15)];
    }
    for (; wt < tiles; wt += NWP) {
        int wn = wt + NWP;
        int sv_n = 0, dv_n = 0;
        if (wn < tiles) {
            sv_n = src[(size_t)wn * 16 + (lane & 15)];
            dv_n = dst[(size_t)wn * 16 + (lane & 15)];
        }
        __syncwarp();
#pragma unroll
        for (int it = 0; it < 8; it++) {
            int j = it * 32 + lane;
            int er = j >> 4;
            int k4 = j & 15;
            int s = __shfl_sync(0xffffffffu, sval, er);
            float4 a = nf4[(size_t)s * 16 + k4];
            float4 b = df4[((size_t)wt * 16 + er) * 16 + k4];
            float4 v = make_float4(a.x * b.x, a.y * b.y, a.z * b.z, a.w * b.w);
            uint2 hi, lo;
            split4(v, hi, lo);
            *reinterpret_cast<uint2*>(&xsh[wblk + er * SP + k4 * 4]) = hi;
            *reinterpret_cast<uint2*>(&xsh[wblk + 1152 + er * SP + k4 * 4]) = lo;
        }
        __syncwarp();

        float acc[8][4];
        ZERO_ACC(acc)
        mma_mainloop(aHi, whl, lane, acc);

        int dA = __shfl_sync(0xffffffffu, dval, r);
        int dB = __shfl_sync(0xffffffffu, dval, r + 8);
        float* pA = Cout + (size_t)dA * BASIS;
        float* pB = Cout + (size_t)dB * BASIS;
#pragma unroll
        for (int nt = 0; nt < 8; nt++) {
            float t0 = fast_tanh(acc[nt][0]);
            float t1 = fast_tanh(acc[nt][1]);
            float t2 = fast_tanh(acc[nt][2]);
            float t3 = fast_tanh(acc[nt][3]);
            float p0 = __shfl_xor_sync(0xffffffffu, t0, 1);
            float p1 = __shfl_xor_sync(0xffffffffu, t1, 1);
            float p2 = __shfl_xor_sync(0xffffffffu, t2, 1);
            float p3 = __shfl_xor_sync(0xffffffffu, t3, 1);
            if ((lane & 1) == 0) {
                int col = nt * 8 + 2 * c;   // c even here
                red_add_v4(pA + col, t0, t1, p0, p1);
                red_add_v4(pB + col, t2, t3, p2, p3);
            }
        }
        sval = sv_n;
        dval = dv_n;
    }
}

// Readout: out[batch[n]] += tanh(C@W1+b1)@W2 + b2
__global__ void __launch_bounds__(256, 3) k_readout(const float* __restrict__ C,
                                                    const int* __restrict__ batch,
                                                    const float* __restrict__ b1,
                                                    const float* __restrict__ W2,
                                                    const float* __restrict__ b2,
                                                    float* __restrict__ out) {
    extern __shared__ char smc[];
    __half* xsh = reinterpret_cast<__half*>(smc);
    uint4* whl = reinterpret_cast<uint4*>(smc + 36864);            // [2048]
    float4* W2s = reinterpret_cast<float4*>(smc + 36864 + 32768);  // [128]
    float* b1s = reinterpret_cast<float*>(smc + 36864 + 32768 + 2048);  // [128]

    int t = threadIdx.x;
    int lane = t & 31;
    int w = t >> 5;
    int wblk = w * WBLK_H;

    for (int i = t; i < 2048; i += 256) whl[i] = g_W1[i];
    if (t < HID) { W2s[t] = reinterpret_cast<const float4*>(W2)[t]; b1s[t] = b1[t]; }
    __syncthreads();

    LDM_ROLE(lane, rowoff, koff)
    uint32_t aHi = (uint32_t)__cvta_generic_to_shared(xsh) +
                   (unsigned)(wblk + rowoff * SP + koff) * 2u;

    float4 b2v = *reinterpret_cast<const float4*>(b2);
    int warpId = blockIdx.x * 8 + w;
    const int NWP = GRID * 8;
    int tiles = (NN + 15) / 16;
    const float4* in4 = reinterpret_cast<const float4*>(C);
    int r = lane >> 2, c = lane & 3;

    for (int wt = warpId; wt < tiles; wt += NWP) {
        int n0 = wt * 16;
        int bi = n0 + (lane & 15);
        int bval = batch[bi < NN ? bi : NN - 1];
        __syncwarp();
#pragma unroll
        for (int it = 0; it < 8; it++) {
            int j = it * 32 + lane;
            int e = j >> 4;
            int k4 = j & 15;
            float4 v = make_float4(0.f, 0.f, 0.f, 0.f);
            if (n0 + e < NN) v = in4[(size_t)(n0 + e) * 16 + k4];
            uint2 hi, lo;
            split4(v, hi, lo);
            *reinterpret_cast<uint2*>(&xsh[wblk + e * SP + k4 * 4]) = hi;
            *reinterpret_cast<uint2*>(&xsh[wblk + 1152 + e * SP + k4 * 4]) = lo;
        }
        __syncwarp();

        float o[2][4];
#pragma unroll
        for (int i = 0; i < 2; i++)
#pragma unroll
            for (int q = 0; q < 4; q++) o[i][q] = 0.0f;

#pragma unroll
        for (int hf = 0; hf < 2; hf++) {
            float acc[8][4];
            ZERO_ACC(acc)
            mma_mainloop(aHi, whl + hf * 1024, lane, acc);
#pragma unroll
            for (int nt = 0; nt < 8; nt++) {
                int col = hf * 64 + nt * 8 + 2 * c;
                float t0 = fast_tanh(acc[nt][0] + b1s[col]);
                float t1 = fast_tanh(acc[nt][1] + b1s[col + 1]);
                float t2 = fast_tanh(acc[nt][2] + b1s[col]);
                float t3 = fast_tanh(acc[nt][3] + b1s[col + 1]);
                float4 wa = W2s[col];
                float4 wc = W2s[col + 1];
                o[0][0] += t0 * wa.x + t1 * wc.x;
                o[0][1] += t0 * wa.y + t1 * wc.y;
                o[0][2] += t0 * wa.z + t1 * wc.z;
                o[0][3] += t0 * wa.w + t1 * wc.w;
                o[1][0] += t2 * wa.x + t3 * wc.x;
                o[1][1] += t2 * wa.y + t3 * wc.y;
                o[1][2] += t2 * wa.z + t3 * wc.z;
                o[1][3] += t2 * wa.w + t3 * wc.w;
            }
        }
#pragma unroll
        for (int i = 0; i < 2; i++)
#pragma unroll
            for (int q = 0; q < 4; q++) {
                o[i][q] += __shfl_xor_sync(0xffffffffu, o[i][q], 1);
                o[i][q] += __shfl_xor_sync(0xffffffffu, o[i][q], 2);
            }
        int g0 = __shfl_sync(0xffffffffu, bval, r);
        int g1 = __shfl_sync(0xffffffffu, bval, r + 8);
        if (c == 0) {
            if (n0 + r < NN)
                red_add_v4(out + (size_t)g0 * 4,
                           o[0][0] + b2v.x, o[0][1] + b2v.y,
                           o[0][2] + b2v.z, o[0][3] + b2v.w);
            if (n0 + r + 8 < NN)
                red_add_v4(out + (size_t)g1 * 4,
                           o[1][0] + b2v.x, o[1][1] + b2v.y,
                           o[1][2] + b2v.z, o[1][3] + b2v.w);
        }
    }
}

extern "C" void kernel_launch(void* const* d_in, const int* in_sizes, int n_in,
                              void* d_out, int out_size) {
    const int*   Z         = (const int*)d_in[0];
    const int*   ei        = (const int*)d_in[1];
    const float* edge_attr = (const float*)d_in[2];
    const int*   batch     = (const int*)d_in[3];
    const float* embed     = (const float*)d_in[4];
    const float* cfW       = (const float*)d_in[5];
    const float* cfb       = (const float*)d_in[6];
    const float* dfW       = (const float*)d_in[7];
    const float* dfb       = (const float*)d_in[8];
    const float* fcW       = (const float*)d_in[9];
    const float* W1        = (const float*)d_in[10];
    const float* b1        = (const float*)d_in[11];
    const float* W2        = (const float*)d_in[12];
    const float* b2        = (const float*)d_in[13];
    const int* src = ei;
    const int* dst = ei + NE;

    float *Ca, *nf, *dfeat;
    cudaGetSymbolAddress((void**)&Ca, g_Ca);
    cudaGetSymbolAddress((void**)&nf, g_nf);
    cudaGetSymbolAddress((void**)&dfeat, g_dfeat);

    const int SM_GEMM = 36864 + 16384 + 256;            // 53504
    const int SM_EDGE = 36864 + 16384;                   // 53248
    const int SM_RO   = 36864 + 32768 + 2048 + 512;      // 72192
    cudaFuncSetAttribute(k_dfeat, cudaFuncAttributeMaxDynamicSharedMemorySize, SM_GEMM);
    cudaFuncSetAttribute(k_nodemv, cudaFuncAttributeMaxDynamicSharedMemorySize, SM_GEMM);
    cudaFuncSetAttribute(k_edge, cudaFuncAttributeMaxDynamicSharedMemorySize, SM_EDGE);
    cudaFuncSetAttribute(k_readout, cudaFuncAttributeMaxDynamicSharedMemorySize, SM_RO);

    k_prep<<<1, 256>>>(fcW, dfW, cfW, W1);
    k_init_C<<<(NN * BASIS + 255) / 256, 256>>>(Z, embed, Ca);
    k_dfeat<<<GRID, 256, SM_GEMM>>>(edge_attr, dfb, dfeat);

    for (int t = 0; t < 3; t++) {
        k_nodemv<<<GRID, 256, SM_GEMM>>>(Ca, cfb, nf);
        k_edge<<<GRID, 256, SM_EDGE>>>(nf, dfeat, src, dst, Ca);
    }

    k_zero<<<(NG * 4 + 255) / 256, 256>>>((float*)d_out, NG * 4);
    k_readout<<<GRID, 256, SM_RO>>>(Ca, batch, b1, W2, b2, (float*)d_out);
}